// round 1
// baseline (speedup 1.0000x reference)
#include <cuda_runtime.h>
#include <cuda_bf16.h>

// ---------------------------------------------------------------------------
// AttentionGNN baseline (Round 0): fp32 SIMT tiled GEMMs + row softmax.
//
//   q = text@Wq+bq ; k = text@Wk+bk ; v = text@Wv+bv        (pass 1, x3)
//   S = q @ k^T                                             (pass 2, NT gemm)
//   attn = softmax(S / 16)   (in place)                     (pass 3)
//   new_adj = attn @ adj     -> d_out[B*N*D ...]            (pass 4, NN gemm)
//   output  = new_adj @ v    -> d_out[0 ...]                (pass 5, NN gemm)
//
// Shapes: B=8, N=2048, D=256.  TEMP = sqrt(256) = 16.
// ---------------------------------------------------------------------------

#define B_   8
#define N_   2048
#define D_   256

#define BM 128
#define BN 128
#define BK 8
#define TM 8
#define TN 8

// Scratch (device globals; no runtime allocation allowed)
__device__ float g_q[(size_t)B_ * N_ * D_];                 // 16 MB
__device__ float g_k[(size_t)B_ * N_ * D_];                 // 16 MB
__device__ float g_v[(size_t)B_ * N_ * D_];                 // 16 MB
__device__ float g_s[(size_t)B_ * N_ * N_];                 // 134 MB (scores/attn)

// ---------------------------------------------------------------------------
// Tiled GEMM: C[M,N] = A[M,K] @ op(B) (+ bias[col])
//   TRANSB = 0: B is [K,N] row-major
//   TRANSB = 1: B is [N,K] row-major (i.e. C = A @ B^T)
// Batched via blockIdx.z with element strides sA/sB/sC.
// Requires: M % 128 == 0, N % 128 == 0, K % 8 == 0, 16B-aligned pointers.
// ---------------------------------------------------------------------------
template <int TRANSB>
__global__ __launch_bounds__(256)
void gemm_kernel(const float* __restrict__ A, const float* __restrict__ B,
                 float* __restrict__ C, const float* __restrict__ bias,
                 int M, int N, int K,
                 long long sA, long long sB, long long sC)
{
    __shared__ float As[BK][BM];
    __shared__ float Bs[BK][BN];

    const int tid = threadIdx.x;

    const float* Ab = A + (long long)blockIdx.z * sA
                        + (long long)(blockIdx.y * BM) * K;
    const float* Bb;
    if (TRANSB)
        Bb = B + (long long)blockIdx.z * sB + (long long)(blockIdx.x * BN) * K;
    else
        Bb = B + (long long)blockIdx.z * sB + (blockIdx.x * BN);
    float* Cb = C + (long long)blockIdx.z * sC;

    // A-tile loader: 128 rows x 8 cols; thread -> (row, 4-col quad)
    const int arow  = tid >> 1;
    const int aquad = (tid & 1) * 4;
    // B-tile loader (NN): 8 rows x 128 cols
    const int brow = tid >> 5;
    const int bcol = (tid & 31) * 4;
    // B-tile loader (NT): 128 n-rows x 8 k-cols (same shape as A loader)
    const int nrow  = tid >> 1;
    const int nquad = (tid & 1) * 4;

    const int ty = tid >> 4;   // 0..15
    const int tx = tid & 15;   // 0..15

    float acc[TM][TN];
    #pragma unroll
    for (int i = 0; i < TM; ++i)
        #pragma unroll
        for (int j = 0; j < TN; ++j) acc[i][j] = 0.0f;

    const int KT = K / BK;

    // prefetch tile 0 into registers
    float4 aReg = *(const float4*)(Ab + (long long)arow * K + aquad);
    float4 bReg;
    if (TRANSB)
        bReg = *(const float4*)(Bb + (long long)nrow * K + nquad);
    else
        bReg = *(const float4*)(Bb + (long long)brow * N + bcol);

    for (int kt = 0; kt < KT; ++kt) {
        // commit prefetched tile to smem
        As[aquad + 0][arow] = aReg.x;
        As[aquad + 1][arow] = aReg.y;
        As[aquad + 2][arow] = aReg.z;
        As[aquad + 3][arow] = aReg.w;
        if (TRANSB) {
            Bs[nquad + 0][nrow] = bReg.x;
            Bs[nquad + 1][nrow] = bReg.y;
            Bs[nquad + 2][nrow] = bReg.z;
            Bs[nquad + 3][nrow] = bReg.w;
        } else {
            *(float4*)&Bs[brow][bcol] = bReg;
        }
        __syncthreads();

        // prefetch next tile (overlaps with FFMA below)
        if (kt + 1 < KT) {
            const int k0 = (kt + 1) * BK;
            aReg = *(const float4*)(Ab + (long long)arow * K + k0 + aquad);
            if (TRANSB)
                bReg = *(const float4*)(Bb + (long long)nrow * K + k0 + nquad);
            else
                bReg = *(const float4*)(Bb + (long long)(k0 + brow) * N + bcol);
        }

        #pragma unroll
        for (int kk = 0; kk < BK; ++kk) {
            float ar[TM], br[TN];
            *(float4*)(ar)     = *(const float4*)&As[kk][ty * TM];
            *(float4*)(ar + 4) = *(const float4*)&As[kk][ty * TM + 4];
            *(float4*)(br)     = *(const float4*)&Bs[kk][tx * TN];
            *(float4*)(br + 4) = *(const float4*)&Bs[kk][tx * TN + 4];
            #pragma unroll
            for (int i = 0; i < TM; ++i)
                #pragma unroll
                for (int j = 0; j < TN; ++j)
                    acc[i][j] = fmaf(ar[i], br[j], acc[i][j]);
        }
        __syncthreads();
    }

    // epilogue
    const int crow0 = blockIdx.y * BM + ty * TM;
    const int ccol0 = blockIdx.x * BN + tx * TN;
    float bcache[TN];
    if (bias) {
        #pragma unroll
        for (int j = 0; j < TN; ++j) bcache[j] = bias[ccol0 + j];
    } else {
        #pragma unroll
        for (int j = 0; j < TN; ++j) bcache[j] = 0.0f;
    }
    #pragma unroll
    for (int i = 0; i < TM; ++i) {
        float4 v0 = make_float4(acc[i][0] + bcache[0], acc[i][1] + bcache[1],
                                acc[i][2] + bcache[2], acc[i][3] + bcache[3]);
        float4 v1 = make_float4(acc[i][4] + bcache[4], acc[i][5] + bcache[5],
                                acc[i][6] + bcache[6], acc[i][7] + bcache[7]);
        float* crow = Cb + (long long)(crow0 + i) * N + ccol0;
        *(float4*)(crow)     = v0;
        *(float4*)(crow + 4) = v1;
    }
}

// ---------------------------------------------------------------------------
// Row softmax over rows of length 2048, applying scale before softmax.
// One block (256 threads) per row; each thread owns 8 elements in registers.
// ---------------------------------------------------------------------------
__global__ __launch_bounds__(256)
void softmax_rows(float* __restrict__ S, float scale)
{
    __shared__ float red[256];
    const int tid = threadIdx.x;
    float* p = S + (long long)blockIdx.x * N_;

    float vals[8];
    float m = -1e30f;
    #pragma unroll
    for (int i = 0; i < 8; ++i) {
        vals[i] = p[tid + 256 * i] * scale;
        m = fmaxf(m, vals[i]);
    }
    red[tid] = m;
    __syncthreads();
    #pragma unroll
    for (int s = 128; s > 0; s >>= 1) {
        if (tid < s) red[tid] = fmaxf(red[tid], red[tid + s]);
        __syncthreads();
    }
    m = red[0];
    __syncthreads();

    float sum = 0.0f;
    #pragma unroll
    for (int i = 0; i < 8; ++i) {
        vals[i] = __expf(vals[i] - m);
        sum += vals[i];
    }
    red[tid] = sum;
    __syncthreads();
    #pragma unroll
    for (int s = 128; s > 0; s >>= 1) {
        if (tid < s) red[tid] += red[tid + s];
        __syncthreads();
    }
    const float inv = 1.0f / red[0];
    #pragma unroll
    for (int i = 0; i < 8; ++i)
        p[tid + 256 * i] = vals[i] * inv;
}

// ---------------------------------------------------------------------------
extern "C" void kernel_launch(void* const* d_in, const int* in_sizes, int n_in,
                              void* d_out, int out_size)
{
    const float* text = (const float*)d_in[0];  // [8,2048,256]
    const float* adj  = (const float*)d_in[1];  // [8,2048,2048]
    const float* Wq   = (const float*)d_in[2];  // [256,256]
    const float* bq   = (const float*)d_in[3];  // [256]
    const float* Wk   = (const float*)d_in[4];
    const float* bk   = (const float*)d_in[5];
    const float* Wv   = (const float*)d_in[6];
    const float* bv   = (const float*)d_in[7];

    float* out     = (float*)d_out;                          // [8,2048,256]
    float* new_adj = out + (long long)B_ * N_ * D_;          // [8,2048,2048]

    float *pq, *pk, *pv, *ps;
    cudaGetSymbolAddress((void**)&pq, g_q);
    cudaGetSymbolAddress((void**)&pk, g_k);
    cudaGetSymbolAddress((void**)&pv, g_v);
    cudaGetSymbolAddress((void**)&ps, g_s);

    const dim3 t(256);
    const long long sQ = (long long)N_ * D_;   // per-batch q/k/v stride
    const long long sS = (long long)N_ * N_;   // per-batch score/adj stride

    // Pass 1: QKV projections (batch folded into M; weights shared)
    {
        dim3 g(D_ / BN, (B_ * N_) / BM, 1);    // (2, 128, 1)
        gemm_kernel<0><<<g, t>>>(text, Wq, pq, bq, B_ * N_, D_, D_, 0, 0, 0);
        gemm_kernel<0><<<g, t>>>(text, Wk, pk, bk, B_ * N_, D_, D_, 0, 0, 0);
        gemm_kernel<0><<<g, t>>>(text, Wv, pv, bv, B_ * N_, D_, D_, 0, 0, 0);
    }

    // Pass 2: S = q @ k^T  (NT, batched)
    {
        dim3 g(N_ / BN, N_ / BM, B_);          // (16, 16, 8)
        gemm_kernel<1><<<g, t>>>(pq, pk, ps, nullptr, N_, N_, D_, sQ, sQ, sS);
    }

    // Pass 3: attn = softmax(S / 16), in place
    softmax_rows<<<B_ * N_, t>>>(ps, 1.0f / 16.0f);

    // Pass 4: new_adj = attn @ adj  (NN, batched) -> d_out second region
    {
        dim3 g(N_ / BN, N_ / BM, B_);          // (16, 16, 8)
        gemm_kernel<0><<<g, t>>>(ps, adj, new_adj, nullptr, N_, N_, N_, sS, sS, sS);
    }

    // Pass 5: output = new_adj @ v  (NN, batched) -> d_out first region
    {
        dim3 g(D_ / BN, N_ / BM, B_);          // (2, 16, 8)
        gemm_kernel<0><<<g, t>>>(new_adj, pv, out, nullptr, N_, D_, N_, sS, sQ, sQ);
    }
}

// round 3
// speedup vs baseline: 2.6681x; 2.6681x over previous
#include <cuda_runtime.h>
#include <cuda_bf16.h>
#include <cstdint>

// ---------------------------------------------------------------------------
// AttentionGNN Round 2:
//   pass 1: q,k,v = text@W*+b*         fp32 SIMT gemm
//   pass 2: S = q @ k^T                fp32 SIMT gemm
//   pass 3: attn = softmax(S/16)       fp32 -> bf16
//   pass 3b: adjT = transpose(adj)     fp32 -> bf16 (K-major)
//   pass 4: new_adj = attn @ adjT^T    HMMA mma.sync bf16 (tcgen05 PTX is
//                                      sm_103a-gated; harness targets sm_103)
//   pass 5: output = new_adj @ v       fp32 SIMT gemm
// ---------------------------------------------------------------------------

#define B_   8
#define N_   2048
#define D_   256

#define BM 128
#define BN 128
#define BK 8
#define TM 8
#define TN 8

__device__ float g_q[(size_t)B_ * N_ * D_];
__device__ float g_k[(size_t)B_ * N_ * D_];
__device__ float g_v[(size_t)B_ * N_ * D_];
__device__ float g_s[(size_t)B_ * N_ * N_];
__device__ __nv_bfloat16 g_attn[(size_t)B_ * N_ * N_];
__device__ __nv_bfloat16 g_adjT[(size_t)B_ * N_ * N_];

// ===========================================================================
// helpers
// ===========================================================================
__device__ __forceinline__ uint32_t smem_u32(const void* p) {
    uint32_t a;
    asm("{ .reg .u64 t; cvta.to.shared.u64 t, %1; cvt.u32.u64 %0, t; }"
        : "=r"(a) : "l"(p));
    return a;
}

#define SMEM_SWIZZLE_128B(off) ((off) ^ (((off) >> 3) & 0x70))

#define CP_ASYNC_16(dst, src) \
    asm volatile("cp.async.cg.shared.global [%0], [%1], 16;" \
                 :: "r"(dst), "l"(src) : "memory")
#define CP_ASYNC_COMMIT() asm volatile("cp.async.commit_group;" ::: "memory")
#define CP_ASYNC_WAIT_ALL() asm volatile("cp.async.wait_group 0;" ::: "memory")

#define LDMATRIX_X4(r0, r1, r2, r3, addr) \
    asm volatile("ldmatrix.sync.aligned.m8n8.x4.shared.b16 {%0,%1,%2,%3}, [%4];" \
                 : "=r"(r0), "=r"(r1), "=r"(r2), "=r"(r3) : "r"(addr))

#define MMA_BF16(d, a, b) \
    asm volatile("mma.sync.aligned.m16n8k16.row.col.f32.bf16.bf16.f32 " \
                 "{%0,%1,%2,%3}, {%4,%5,%6,%7}, {%8,%9}, {%0,%1,%2,%3};" \
                 : "+f"((d)[0]), "+f"((d)[1]), "+f"((d)[2]), "+f"((d)[3]) \
                 : "r"((a)[0]), "r"((a)[1]), "r"((a)[2]), "r"((a)[3]), \
                   "r"((b)[0]), "r"((b)[1]))

// ===========================================================================
// Pass 4: C[b][m][n] = sum_k A[b][m][k] * Bt[b][n][k]   (bf16 HMMA, fp32 acc)
// CTA tile 128x128, K-chunk 64. 8 warps: 2(m) x 4(n), warp tile 64x32.
// Smem: SW128-swizzled 128x64 bf16 tiles (128B rows), double buffered (64KB).
// ===========================================================================
#define HKITER (N_ / 64)            // 32
#define HTILE  16384                // bytes per 128x64 bf16 tile
#define SMEM_HMMA (2 * 2 * HTILE + 1024)

__device__ __forceinline__ void load_tile_128x64(
    uint32_t s, const __nv_bfloat16* __restrict__ g, int tid)
{
    const char* gc = (const char*)g;
    #pragma unroll
    for (int i = 0; i < 4; ++i) {
        int id  = tid + 256 * i;
        int row = id >> 3;
        int c   = (id & 7) * 16;
        CP_ASYNC_16(s + SMEM_SWIZZLE_128B(row * 128 + c),
                    gc + (size_t)row * (N_ * 2) + c);
    }
}

__global__ void __launch_bounds__(256, 2)
hmma_attn_adj(const __nv_bfloat16* __restrict__ A,   // attn [B,N,N] k-major
              const __nv_bfloat16* __restrict__ Bt,  // adjT [B,N,N] k-major
              float* __restrict__ C)                 // new_adj [B,N,N]
{
    extern __shared__ char dsm[];
    const uint32_t base = (smem_u32(dsm) + 1023) & ~1023u;

    const int tid  = threadIdx.x;
    const int lane = tid & 31;
    const int wid  = tid >> 5;
    const int wm0  = (wid & 1) * 64;    // warp m offset in tile
    const int wn0  = (wid >> 1) * 32;   // warp n offset in tile
    const int lr   = lane & 15;         // ldmatrix row-within-16
    const int lc   = lane >> 4;         // ldmatrix 16B-chunk select

    const int b  = blockIdx.z;
    const int m0 = blockIdx.y * 128;
    const int n0 = blockIdx.x * 128;
    const __nv_bfloat16* Ab = A  + ((size_t)b * N_ + m0) * N_;
    const __nv_bfloat16* Bb = Bt + ((size_t)b * N_ + n0) * N_;

    float acc[4][4][4];
    #pragma unroll
    for (int i = 0; i < 4; ++i)
        #pragma unroll
        for (int j = 0; j < 4; ++j)
            #pragma unroll
            for (int r = 0; r < 4; ++r) acc[i][j][r] = 0.0f;

    // prologue: tile 0 -> buffer 0
    load_tile_128x64(base,         Ab, tid);
    load_tile_128x64(base + HTILE, Bb, tid);
    CP_ASYNC_COMMIT();
    CP_ASYNC_WAIT_ALL();
    __syncthreads();

    for (int kt = 0; kt < HKITER; ++kt) {
        const int buf = kt & 1;
        const uint32_t cA = base + buf * (2 * HTILE);
        const uint32_t cB = cA + HTILE;

        if (kt + 1 < HKITER) {
            const uint32_t nA = base + (buf ^ 1) * (2 * HTILE);
            load_tile_128x64(nA,         Ab + (size_t)(kt + 1) * 64, tid);
            load_tile_128x64(nA + HTILE, Bb + (size_t)(kt + 1) * 64, tid);
            CP_ASYNC_COMMIT();
        }

        #pragma unroll
        for (int ks = 0; ks < 4; ++ks) {
            uint32_t af[4][4];
            uint32_t bf[4][2];
            const int csel = ks * 2 + lc;

            #pragma unroll
            for (int mi = 0; mi < 4; ++mi) {
                const int row = wm0 + mi * 16 + lr;
                const uint32_t addr =
                    cA + SMEM_SWIZZLE_128B(row * 128 + csel * 16);
                LDMATRIX_X4(af[mi][0], af[mi][1], af[mi][2], af[mi][3], addr);
            }
            #pragma unroll
            for (int nb = 0; nb < 2; ++nb) {
                const int row = wn0 + nb * 16 + lr;
                const uint32_t addr =
                    cB + SMEM_SWIZZLE_128B(row * 128 + csel * 16);
                uint32_t r0, r1, r2, r3;
                LDMATRIX_X4(r0, r1, r2, r3, addr);
                bf[nb * 2][0]     = r0;  bf[nb * 2][1]     = r2;
                bf[nb * 2 + 1][0] = r1;  bf[nb * 2 + 1][1] = r3;
            }

            #pragma unroll
            for (int mi = 0; mi < 4; ++mi)
                #pragma unroll
                for (int nj = 0; nj < 4; ++nj)
                    MMA_BF16(acc[mi][nj], af[mi], bf[nj]);
        }

        CP_ASYNC_WAIT_ALL();
        __syncthreads();
    }

    // epilogue: fp32 stores
    float* Cb = C + ((size_t)b * N_ + m0 + wm0) * N_ + n0 + wn0;
    const int r     = lane >> 2;
    const int cpair = (lane & 3) * 2;
    #pragma unroll
    for (int mi = 0; mi < 4; ++mi) {
        #pragma unroll
        for (int nj = 0; nj < 4; ++nj) {
            float* p = Cb + (size_t)(mi * 16 + r) * N_ + nj * 8 + cpair;
            *(float2*)p            = make_float2(acc[mi][nj][0], acc[mi][nj][1]);
            *(float2*)(p + 8 * N_) = make_float2(acc[mi][nj][2], acc[mi][nj][3]);
        }
    }
}

// ===========================================================================
// fp32 SIMT tiled GEMM (passes 1, 2, 5)
// ===========================================================================
template <int TRANSB>
__global__ __launch_bounds__(256)
void gemm_kernel(const float* __restrict__ A, const float* __restrict__ B,
                 float* __restrict__ C, const float* __restrict__ bias,
                 int M, int N, int K,
                 long long sA, long long sB, long long sC)
{
    __shared__ float As[BK][BM];
    __shared__ float Bs[BK][BN];

    const int tid = threadIdx.x;

    const float* Ab = A + (long long)blockIdx.z * sA
                        + (long long)(blockIdx.y * BM) * K;
    const float* Bb;
    if (TRANSB)
        Bb = B + (long long)blockIdx.z * sB + (long long)(blockIdx.x * BN) * K;
    else
        Bb = B + (long long)blockIdx.z * sB + (blockIdx.x * BN);
    float* Cb = C + (long long)blockIdx.z * sC;

    const int arow  = tid >> 1;
    const int aquad = (tid & 1) * 4;
    const int brow = tid >> 5;
    const int bcol = (tid & 31) * 4;
    const int nrow  = tid >> 1;
    const int nquad = (tid & 1) * 4;

    const int ty = tid >> 4;
    const int tx = tid & 15;

    float acc[TM][TN];
    #pragma unroll
    for (int i = 0; i < TM; ++i)
        #pragma unroll
        for (int j = 0; j < TN; ++j) acc[i][j] = 0.0f;

    const int KT = K / BK;

    float4 aReg = *(const float4*)(Ab + (long long)arow * K + aquad);
    float4 bReg;
    if (TRANSB)
        bReg = *(const float4*)(Bb + (long long)nrow * K + nquad);
    else
        bReg = *(const float4*)(Bb + (long long)brow * N + bcol);

    for (int kt = 0; kt < KT; ++kt) {
        As[aquad + 0][arow] = aReg.x;
        As[aquad + 1][arow] = aReg.y;
        As[aquad + 2][arow] = aReg.z;
        As[aquad + 3][arow] = aReg.w;
        if (TRANSB) {
            Bs[nquad + 0][nrow] = bReg.x;
            Bs[nquad + 1][nrow] = bReg.y;
            Bs[nquad + 2][nrow] = bReg.z;
            Bs[nquad + 3][nrow] = bReg.w;
        } else {
            *(float4*)&Bs[brow][bcol] = bReg;
        }
        __syncthreads();

        if (kt + 1 < KT) {
            const int k0 = (kt + 1) * BK;
            aReg = *(const float4*)(Ab + (long long)arow * K + k0 + aquad);
            if (TRANSB)
                bReg = *(const float4*)(Bb + (long long)nrow * K + k0 + nquad);
            else
                bReg = *(const float4*)(Bb + (long long)(k0 + brow) * N + bcol);
        }

        #pragma unroll
        for (int kk = 0; kk < BK; ++kk) {
            float ar[TM], br[TN];
            *(float4*)(ar)     = *(const float4*)&As[kk][ty * TM];
            *(float4*)(ar + 4) = *(const float4*)&As[kk][ty * TM + 4];
            *(float4*)(br)     = *(const float4*)&Bs[kk][tx * TN];
            *(float4*)(br + 4) = *(const float4*)&Bs[kk][tx * TN + 4];
            #pragma unroll
            for (int i = 0; i < TM; ++i)
                #pragma unroll
                for (int j = 0; j < TN; ++j)
                    acc[i][j] = fmaf(ar[i], br[j], acc[i][j]);
        }
        __syncthreads();
    }

    const int crow0 = blockIdx.y * BM + ty * TM;
    const int ccol0 = blockIdx.x * BN + tx * TN;
    float bcache[TN];
    if (bias) {
        #pragma unroll
        for (int j = 0; j < TN; ++j) bcache[j] = bias[ccol0 + j];
    } else {
        #pragma unroll
        for (int j = 0; j < TN; ++j) bcache[j] = 0.0f;
    }
    #pragma unroll
    for (int i = 0; i < TM; ++i) {
        float4 v0 = make_float4(acc[i][0] + bcache[0], acc[i][1] + bcache[1],
                                acc[i][2] + bcache[2], acc[i][3] + bcache[3]);
        float4 v1 = make_float4(acc[i][4] + bcache[4], acc[i][5] + bcache[5],
                                acc[i][6] + bcache[6], acc[i][7] + bcache[7]);
        float* crow = Cb + (long long)(crow0 + i) * N + ccol0;
        *(float4*)(crow)     = v0;
        *(float4*)(crow + 4) = v1;
    }
}

// ===========================================================================
// Row softmax (scale then softmax), fp32 in -> bf16 out
// ===========================================================================
__global__ __launch_bounds__(256)
void softmax_rows(const float* __restrict__ S, __nv_bfloat16* __restrict__ O,
                  float scale)
{
    __shared__ float red[256];
    const int tid = threadIdx.x;
    const float* p = S + (long long)blockIdx.x * N_;
    __nv_bfloat16* o = O + (long long)blockIdx.x * N_;

    float vals[8];
    float m = -1e30f;
    #pragma unroll
    for (int i = 0; i < 8; ++i) {
        vals[i] = p[tid + 256 * i] * scale;
        m = fmaxf(m, vals[i]);
    }
    red[tid] = m;
    __syncthreads();
    #pragma unroll
    for (int s = 128; s > 0; s >>= 1) {
        if (tid < s) red[tid] = fmaxf(red[tid], red[tid + s]);
        __syncthreads();
    }
    m = red[0];
    __syncthreads();

    float sum = 0.0f;
    #pragma unroll
    for (int i = 0; i < 8; ++i) {
        vals[i] = __expf(vals[i] - m);
        sum += vals[i];
    }
    red[tid] = sum;
    __syncthreads();
    #pragma unroll
    for (int s = 128; s > 0; s >>= 1) {
        if (tid < s) red[tid] += red[tid + s];
        __syncthreads();
    }
    const float inv = 1.0f / red[0];
    #pragma unroll
    for (int i = 0; i < 8; ++i)
        o[tid + 256 * i] = __float2bfloat16(vals[i] * inv);
}

// ===========================================================================
// adj fp32 [b][k][n] -> adjT bf16 [b][n][k]
// ===========================================================================
__global__ __launch_bounds__(256)
void transpose_bf16(const float* __restrict__ A, __nv_bfloat16* __restrict__ T)
{
    __shared__ float t[32][33];
    const int b  = blockIdx.z;
    const int x0 = blockIdx.x * 32;
    const int y0 = blockIdx.y * 32;
    const float* Ab = A + (size_t)b * N_ * N_;
    __nv_bfloat16* Tb = T + (size_t)b * N_ * N_;
    const int tx = threadIdx.x & 31;
    const int ty = threadIdx.x >> 5;
    #pragma unroll
    for (int j = 0; j < 4; ++j)
        t[ty + 8 * j][tx] = Ab[(size_t)(y0 + ty + 8 * j) * N_ + x0 + tx];
    __syncthreads();
    #pragma unroll
    for (int j = 0; j < 4; ++j)
        Tb[(size_t)(x0 + ty + 8 * j) * N_ + y0 + tx] =
            __float2bfloat16(t[tx][ty + 8 * j]);
}

// ===========================================================================
extern "C" void kernel_launch(void* const* d_in, const int* in_sizes, int n_in,
                              void* d_out, int out_size)
{
    const float* text = (const float*)d_in[0];
    const float* adj  = (const float*)d_in[1];
    const float* Wq   = (const float*)d_in[2];
    const float* bq   = (const float*)d_in[3];
    const float* Wk   = (const float*)d_in[4];
    const float* bk   = (const float*)d_in[5];
    const float* Wv   = (const float*)d_in[6];
    const float* bv   = (const float*)d_in[7];

    float* out     = (float*)d_out;
    float* new_adj = out + (long long)B_ * N_ * D_;

    float *pq, *pk, *pv, *ps;
    __nv_bfloat16 *pattn, *padjT;
    cudaGetSymbolAddress((void**)&pq, g_q);
    cudaGetSymbolAddress((void**)&pk, g_k);
    cudaGetSymbolAddress((void**)&pv, g_v);
    cudaGetSymbolAddress((void**)&ps, g_s);
    cudaGetSymbolAddress((void**)&pattn, g_attn);
    cudaGetSymbolAddress((void**)&padjT, g_adjT);

    cudaFuncSetAttribute(hmma_attn_adj,
                         cudaFuncAttributeMaxDynamicSharedMemorySize, SMEM_HMMA);

    const dim3 t(256);
    const long long sQ = (long long)N_ * D_;
    const long long sS = (long long)N_ * N_;

    // Pass 1: QKV projections
    {
        dim3 g(D_ / BN, (B_ * N_) / BM, 1);
        gemm_kernel<0><<<g, t>>>(text, Wq, pq, bq, B_ * N_, D_, D_, 0, 0, 0);
        gemm_kernel<0><<<g, t>>>(text, Wk, pk, bk, B_ * N_, D_, D_, 0, 0, 0);
        gemm_kernel<0><<<g, t>>>(text, Wv, pv, bv, B_ * N_, D_, D_, 0, 0, 0);
    }

    // Pass 3b: adjT bf16 (independent of passes 1-3)
    {
        dim3 g(N_ / 32, N_ / 32, B_);
        transpose_bf16<<<g, t>>>(adj, padjT);
    }

    // Pass 2: S = q @ k^T (fp32)
    {
        dim3 g(N_ / BN, N_ / BM, B_);
        gemm_kernel<1><<<g, t>>>(pq, pk, ps, nullptr, N_, N_, D_, sQ, sQ, sS);
    }

    // Pass 3: attn = softmax(S/16) -> bf16
    softmax_rows<<<B_ * N_, t>>>(ps, pattn, 1.0f / 16.0f);

    // Pass 4: new_adj = attn @ adjT^T  (bf16 HMMA)
    {
        dim3 g(N_ / 128, N_ / 128, B_);   // (16, 16, 8)
        hmma_attn_adj<<<g, t, SMEM_HMMA>>>(pattn, padjT, new_adj);
    }

    // Pass 5: output = new_adj @ v (fp32)
    {
        dim3 g(D_ / BN, N_ / BM, B_);
        gemm_kernel<0><<<g, t>>>(new_adj, pv, out, nullptr, N_, D_, N_, sS, sQ, sQ);
    }
}

// round 4
// speedup vs baseline: 4.2631x; 1.5978x over previous
#include <cuda_runtime.h>
#include <cuda_bf16.h>
#include <cstdint>

// ---------------------------------------------------------------------------
// AttentionGNN Round 3: all big GEMMs on tensor cores (mma.sync bf16).
//   pass 1: q,k (bf16 out), v (fp32 out) = text@W+b     fp32 SIMT gemm
//   pass 1b: vT_hi/vT_lo = split(transpose(v))          bf16 x2
//   pass 1c: adjT = transpose(adj)                      bf16
//   pass 2: S = q @ k^T                                 bf16 HMMA   (was fp32)
//   pass 3: attn = softmax(S/16) -> bf16
//   pass 4: new_adj = attn @ adjT^T  -> fp32 (+ hi/lo bf16 split)  bf16 HMMA
//   pass 5: out = Ah@Bh + Al@Bh + Ah@Bl  (double-bf16)  HMMA       (was fp32)
// ---------------------------------------------------------------------------

#define B_   8
#define N_   2048
#define D_   256

#define BM 128
#define BN 128
#define BK 8
#define TM 8
#define TN 8

// Scratch (device globals)
__device__ __nv_bfloat16 g_qb [(size_t)B_ * N_ * D_];       // q bf16
__device__ __nv_bfloat16 g_kb [(size_t)B_ * N_ * D_];       // k bf16
__device__ float         g_v  [(size_t)B_ * N_ * D_];       // v fp32
__device__ __nv_bfloat16 g_vth[(size_t)B_ * D_ * N_];       // v^T hi
__device__ __nv_bfloat16 g_vtl[(size_t)B_ * D_ * N_];       // v^T lo
__device__ float         g_s  [(size_t)B_ * N_ * N_];       // scores; later aliased
                                                            // as new_adj hi/lo bf16
__device__ __nv_bfloat16 g_attn[(size_t)B_ * N_ * N_];      // attn bf16
__device__ __nv_bfloat16 g_adjT[(size_t)B_ * N_ * N_];      // adj^T bf16

// ===========================================================================
// helpers
// ===========================================================================
__device__ __forceinline__ uint32_t smem_u32(const void* p) {
    uint32_t a;
    asm("{ .reg .u64 t; cvta.to.shared.u64 t, %1; cvt.u32.u64 %0, t; }"
        : "=r"(a) : "l"(p));
    return a;
}

#define SMEM_SWIZZLE_128B(off) ((off) ^ (((off) >> 3) & 0x70))

#define CP_ASYNC_16(dst, src) \
    asm volatile("cp.async.cg.shared.global [%0], [%1], 16;" \
                 :: "r"(dst), "l"(src) : "memory")
#define CP_ASYNC_COMMIT() asm volatile("cp.async.commit_group;" ::: "memory")
#define CP_ASYNC_WAIT_ALL() asm volatile("cp.async.wait_group 0;" ::: "memory")

#define LDMATRIX_X4(r0, r1, r2, r3, addr) \
    asm volatile("ldmatrix.sync.aligned.m8n8.x4.shared.b16 {%0,%1,%2,%3}, [%4];" \
                 : "=r"(r0), "=r"(r1), "=r"(r2), "=r"(r3) : "r"(addr))

#define MMA_BF16(d, a, b) \
    asm volatile("mma.sync.aligned.m16n8k16.row.col.f32.bf16.bf16.f32 " \
                 "{%0,%1,%2,%3}, {%4,%5,%6,%7}, {%8,%9}, {%0,%1,%2,%3};" \
                 : "+f"((d)[0]), "+f"((d)[1]), "+f"((d)[2]), "+f"((d)[3]) \
                 : "r"((a)[0]), "r"((a)[1]), "r"((a)[2]), "r"((a)[3]), \
                   "r"((b)[0]), "r"((b)[1]))

// ===========================================================================
// Generic NT bf16 HMMA GEMM:  C[b][m][n] = sum_k A[b][m][k] * Bt[b][n][k]
// CTA tile 128x128, K-chunk 64, double-buffered cp.async, SW128 smem.
// SPLIT=1 additionally writes bf16 hi/lo double-bf16 decomposition of C.
// ===========================================================================
#define HTILE 16384
#define SMEM_HMMA (2 * 2 * HTILE + 1024)

__device__ __forceinline__ void load_tile_128x64g(
    uint32_t s, const char* gbase, int ldBytes, int tid)
{
    #pragma unroll
    for (int i = 0; i < 4; ++i) {
        int id  = tid + 256 * i;
        int row = id >> 3;
        int c   = (id & 7) * 16;
        CP_ASYNC_16(s + SMEM_SWIZZLE_128B(row * 128 + c),
                    gbase + (size_t)row * ldBytes + c);
    }
}

template <int SPLIT>
__global__ void __launch_bounds__(256, 2)
hmma_nt(const __nv_bfloat16* __restrict__ A,
        const __nv_bfloat16* __restrict__ Bt,
        float* __restrict__ C,
        __nv_bfloat16* __restrict__ Chi,
        __nv_bfloat16* __restrict__ Clo,
        int kIters, int ldA, int ldB, int ldC,
        long long sA, long long sB, long long sC)
{
    extern __shared__ char dsm[];
    const uint32_t base = (smem_u32(dsm) + 1023) & ~1023u;

    const int tid  = threadIdx.x;
    const int lane = tid & 31;
    const int wid  = tid >> 5;
    const int wm0  = (wid & 1) * 64;
    const int wn0  = (wid >> 1) * 32;
    const int lr   = lane & 15;
    const int lc   = lane >> 4;

    const int b  = blockIdx.z;
    const int m0 = blockIdx.y * 128;
    const int n0 = blockIdx.x * 128;
    const char* Ab = (const char*)(A  + (size_t)b * sA + (size_t)m0 * ldA);
    const char* Bb = (const char*)(Bt + (size_t)b * sB + (size_t)n0 * ldB);
    const int ldAB = ldA * 2;
    const int ldBB = ldB * 2;

    float acc[4][4][4];
    #pragma unroll
    for (int i = 0; i < 4; ++i)
        #pragma unroll
        for (int j = 0; j < 4; ++j)
            #pragma unroll
            for (int r = 0; r < 4; ++r) acc[i][j][r] = 0.0f;

    load_tile_128x64g(base,         Ab, ldAB, tid);
    load_tile_128x64g(base + HTILE, Bb, ldBB, tid);
    CP_ASYNC_COMMIT();
    CP_ASYNC_WAIT_ALL();
    __syncthreads();

    for (int kt = 0; kt < kIters; ++kt) {
        const int buf = kt & 1;
        const uint32_t cA = base + buf * (2 * HTILE);
        const uint32_t cB = cA + HTILE;

        if (kt + 1 < kIters) {
            const uint32_t nA = base + (buf ^ 1) * (2 * HTILE);
            load_tile_128x64g(nA,         Ab + (size_t)(kt + 1) * 128, ldAB, tid);
            load_tile_128x64g(nA + HTILE, Bb + (size_t)(kt + 1) * 128, ldBB, tid);
            CP_ASYNC_COMMIT();
        }

        #pragma unroll
        for (int ks = 0; ks < 4; ++ks) {
            uint32_t af[4][4];
            uint32_t bf[4][2];
            const int csel = ks * 2 + lc;

            #pragma unroll
            for (int mi = 0; mi < 4; ++mi) {
                const int row = wm0 + mi * 16 + lr;
                LDMATRIX_X4(af[mi][0], af[mi][1], af[mi][2], af[mi][3],
                            cA + SMEM_SWIZZLE_128B(row * 128 + csel * 16));
            }
            #pragma unroll
            for (int nb = 0; nb < 2; ++nb) {
                const int row = wn0 + nb * 16 + lr;
                uint32_t r0, r1, r2, r3;
                LDMATRIX_X4(r0, r1, r2, r3,
                            cB + SMEM_SWIZZLE_128B(row * 128 + csel * 16));
                bf[nb * 2][0]     = r0;  bf[nb * 2][1]     = r2;
                bf[nb * 2 + 1][0] = r1;  bf[nb * 2 + 1][1] = r3;
            }

            #pragma unroll
            for (int mi = 0; mi < 4; ++mi)
                #pragma unroll
                for (int nj = 0; nj < 4; ++nj)
                    MMA_BF16(acc[mi][nj], af[mi], bf[nj]);
        }

        CP_ASYNC_WAIT_ALL();
        __syncthreads();
    }

    // epilogue
    const size_t crow = (size_t)b * sC + (size_t)(m0 + wm0) * ldC + n0 + wn0;
    const int r     = lane >> 2;
    const int cpair = (lane & 3) * 2;
    #pragma unroll
    for (int mi = 0; mi < 4; ++mi) {
        #pragma unroll
        for (int nj = 0; nj < 4; ++nj) {
            const size_t off0 = crow + (size_t)(mi * 16 + r) * ldC + nj * 8 + cpair;
            const size_t off1 = off0 + (size_t)8 * ldC;
            *(float2*)(C + off0) = make_float2(acc[mi][nj][0], acc[mi][nj][1]);
            *(float2*)(C + off1) = make_float2(acc[mi][nj][2], acc[mi][nj][3]);
            if (SPLIT) {
                #pragma unroll
                for (int h = 0; h < 2; ++h) {
                    const size_t off = h ? off1 : off0;
                    float a0 = acc[mi][nj][h * 2], a1 = acc[mi][nj][h * 2 + 1];
                    __nv_bfloat16 h0 = __float2bfloat16(a0);
                    __nv_bfloat16 h1 = __float2bfloat16(a1);
                    __nv_bfloat16 l0 = __float2bfloat16(a0 - __bfloat162float(h0));
                    __nv_bfloat16 l1 = __float2bfloat16(a1 - __bfloat162float(h1));
                    __nv_bfloat162 hv; hv.x = h0; hv.y = h1;
                    __nv_bfloat162 lv; lv.x = l0; lv.y = l1;
                    *(__nv_bfloat162*)(Chi + off) = hv;
                    *(__nv_bfloat162*)(Clo + off) = lv;
                }
            }
        }
    }
}

// ===========================================================================
// Pass 5: out[b][m][d] = sum_k (Ah+Al)[m,k] * (Bh+Bl)[d,k]
//       ~= Ah@Bh + Al@Bh + Ah@Bl    (double-bf16, fp32 acc)
// A = new_adj split [B,2048,2048], B = v^T split [B,256,2048], C fp32 [B,2048,256]
// CTA tile 128x128(d), K-chunk 64, 32 k-iters.
// ===========================================================================
#define SMEM_OUT (2 * 4 * HTILE + 1024)

__global__ void __launch_bounds__(256, 1)
hmma_out3(const __nv_bfloat16* __restrict__ Ah,
          const __nv_bfloat16* __restrict__ Al,
          const __nv_bfloat16* __restrict__ Bh,
          const __nv_bfloat16* __restrict__ Bl,
          float* __restrict__ C)
{
    extern __shared__ char dsm[];
    const uint32_t base = (smem_u32(dsm) + 1023) & ~1023u;

    const int tid  = threadIdx.x;
    const int lane = tid & 31;
    const int wid  = tid >> 5;
    const int wm0  = (wid & 1) * 64;
    const int wn0  = (wid >> 1) * 32;
    const int lr   = lane & 15;
    const int lc   = lane >> 4;

    const int b  = blockIdx.z;
    const int m0 = blockIdx.y * 128;
    const int n0 = blockIdx.x * 128;           // d-offset
    const char* Ahb = (const char*)(Ah + ((size_t)b * N_ + m0) * N_);
    const char* Alb = (const char*)(Al + ((size_t)b * N_ + m0) * N_);
    const char* Bhb = (const char*)(Bh + ((size_t)b * D_ + n0) * N_);
    const char* Blb = (const char*)(Bl + ((size_t)b * D_ + n0) * N_);
    const int ldBytes = N_ * 2;

    float acc[4][4][4];
    #pragma unroll
    for (int i = 0; i < 4; ++i)
        #pragma unroll
        for (int j = 0; j < 4; ++j)
            #pragma unroll
            for (int r = 0; r < 4; ++r) acc[i][j][r] = 0.0f;

    load_tile_128x64g(base,             Ahb, ldBytes, tid);
    load_tile_128x64g(base + HTILE,     Alb, ldBytes, tid);
    load_tile_128x64g(base + 2 * HTILE, Bhb, ldBytes, tid);
    load_tile_128x64g(base + 3 * HTILE, Blb, ldBytes, tid);
    CP_ASYNC_COMMIT();
    CP_ASYNC_WAIT_ALL();
    __syncthreads();

    const int KITER = N_ / 64;    // 32
    for (int kt = 0; kt < KITER; ++kt) {
        const int buf = kt & 1;
        const uint32_t cAh = base + buf * (4 * HTILE);
        const uint32_t cAl = cAh + HTILE;
        const uint32_t cBh = cAh + 2 * HTILE;
        const uint32_t cBl = cAh + 3 * HTILE;

        if (kt + 1 < KITER) {
            const uint32_t nx = base + (buf ^ 1) * (4 * HTILE);
            const size_t ko = (size_t)(kt + 1) * 128;
            load_tile_128x64g(nx,             Ahb + ko, ldBytes, tid);
            load_tile_128x64g(nx + HTILE,     Alb + ko, ldBytes, tid);
            load_tile_128x64g(nx + 2 * HTILE, Bhb + ko, ldBytes, tid);
            load_tile_128x64g(nx + 3 * HTILE, Blb + ko, ldBytes, tid);
            CP_ASYNC_COMMIT();
        }

        #pragma unroll
        for (int ks = 0; ks < 4; ++ks) {
            uint32_t afh[4][4], afl[4][4];
            uint32_t bfh[4][2], bfl[4][2];
            const int csel = ks * 2 + lc;

            #pragma unroll
            for (int mi = 0; mi < 4; ++mi) {
                const int row = wm0 + mi * 16 + lr;
                const uint32_t so = SMEM_SWIZZLE_128B(row * 128 + csel * 16);
                LDMATRIX_X4(afh[mi][0], afh[mi][1], afh[mi][2], afh[mi][3], cAh + so);
                LDMATRIX_X4(afl[mi][0], afl[mi][1], afl[mi][2], afl[mi][3], cAl + so);
            }
            #pragma unroll
            for (int nb = 0; nb < 2; ++nb) {
                const int row = wn0 + nb * 16 + lr;
                const uint32_t so = SMEM_SWIZZLE_128B(row * 128 + csel * 16);
                uint32_t r0, r1, r2, r3;
                LDMATRIX_X4(r0, r1, r2, r3, cBh + so);
                bfh[nb * 2][0]     = r0;  bfh[nb * 2][1]     = r2;
                bfh[nb * 2 + 1][0] = r1;  bfh[nb * 2 + 1][1] = r3;
                LDMATRIX_X4(r0, r1, r2, r3, cBl + so);
                bfl[nb * 2][0]     = r0;  bfl[nb * 2][1]     = r2;
                bfl[nb * 2 + 1][0] = r1;  bfl[nb * 2 + 1][1] = r3;
            }

            #pragma unroll
            for (int mi = 0; mi < 4; ++mi)
                #pragma unroll
                for (int nj = 0; nj < 4; ++nj) {
                    MMA_BF16(acc[mi][nj], afh[mi], bfh[nj]);
                    MMA_BF16(acc[mi][nj], afl[mi], bfh[nj]);
                    MMA_BF16(acc[mi][nj], afh[mi], bfl[nj]);
                }
        }

        CP_ASYNC_WAIT_ALL();
        __syncthreads();
    }

    float* Cb = C + ((size_t)b * N_ + m0 + wm0) * D_ + n0 + wn0;
    const int r     = lane >> 2;
    const int cpair = (lane & 3) * 2;
    #pragma unroll
    for (int mi = 0; mi < 4; ++mi) {
        #pragma unroll
        for (int nj = 0; nj < 4; ++nj) {
            float* p = Cb + (size_t)(mi * 16 + r) * D_ + nj * 8 + cpair;
            *(float2*)p            = make_float2(acc[mi][nj][0], acc[mi][nj][1]);
            *(float2*)(p + 8 * D_) = make_float2(acc[mi][nj][2], acc[mi][nj][3]);
        }
    }
}

// ===========================================================================
// fp32 SIMT tiled GEMM (pass 1), templated output type
// ===========================================================================
__device__ __forceinline__ void store8(float* p, const float* v) {
    *(float4*)p       = make_float4(v[0], v[1], v[2], v[3]);
    *(float4*)(p + 4) = make_float4(v[4], v[5], v[6], v[7]);
}
__device__ __forceinline__ void store8(__nv_bfloat16* p, const float* v) {
    __nv_bfloat162 h[4];
    #pragma unroll
    for (int i = 0; i < 4; ++i) {
        h[i].x = __float2bfloat16(v[2 * i]);
        h[i].y = __float2bfloat16(v[2 * i + 1]);
    }
    *(uint4*)p = *(uint4*)h;
}

template <typename OutT>
__global__ __launch_bounds__(256)
void gemm_proj(const float* __restrict__ A, const float* __restrict__ B,
               OutT* __restrict__ C, const float* __restrict__ bias,
               int M, int N, int K)
{
    __shared__ float As[BK][BM];
    __shared__ float Bs[BK][BN];

    const int tid = threadIdx.x;
    const float* Ab = A + (long long)(blockIdx.y * BM) * K;
    const float* Bb = B + (blockIdx.x * BN);

    const int arow  = tid >> 1;
    const int aquad = (tid & 1) * 4;
    const int brow = tid >> 5;
    const int bcol = (tid & 31) * 4;
    const int ty = tid >> 4;
    const int tx = tid & 15;

    float acc[TM][TN];
    #pragma unroll
    for (int i = 0; i < TM; ++i)
        #pragma unroll
        for (int j = 0; j < TN; ++j) acc[i][j] = 0.0f;

    const int KT = K / BK;
    float4 aReg = *(const float4*)(Ab + (long long)arow * K + aquad);
    float4 bReg = *(const float4*)(Bb + (long long)brow * N + bcol);

    for (int kt = 0; kt < KT; ++kt) {
        As[aquad + 0][arow] = aReg.x;
        As[aquad + 1][arow] = aReg.y;
        As[aquad + 2][arow] = aReg.z;
        As[aquad + 3][arow] = aReg.w;
        *(float4*)&Bs[brow][bcol] = bReg;
        __syncthreads();

        if (kt + 1 < KT) {
            const int k0 = (kt + 1) * BK;
            aReg = *(const float4*)(Ab + (long long)arow * K + k0 + aquad);
            bReg = *(const float4*)(Bb + (long long)(k0 + brow) * N + bcol);
        }

        #pragma unroll
        for (int kk = 0; kk < BK; ++kk) {
            float ar[TM], br[TN];
            *(float4*)(ar)     = *(const float4*)&As[kk][ty * TM];
            *(float4*)(ar + 4) = *(const float4*)&As[kk][ty * TM + 4];
            *(float4*)(br)     = *(const float4*)&Bs[kk][tx * TN];
            *(float4*)(br + 4) = *(const float4*)&Bs[kk][tx * TN + 4];
            #pragma unroll
            for (int i = 0; i < TM; ++i)
                #pragma unroll
                for (int j = 0; j < TN; ++j)
                    acc[i][j] = fmaf(ar[i], br[j], acc[i][j]);
        }
        __syncthreads();
    }

    const int crow0 = blockIdx.y * BM + ty * TM;
    const int ccol0 = blockIdx.x * BN + tx * TN;
    float bcache[TN];
    #pragma unroll
    for (int j = 0; j < TN; ++j) bcache[j] = bias[ccol0 + j];
    #pragma unroll
    for (int i = 0; i < TM; ++i) {
        float v[TN];
        #pragma unroll
        for (int j = 0; j < TN; ++j) v[j] = acc[i][j] + bcache[j];
        store8(C + (long long)(crow0 + i) * N + ccol0, v);
    }
}

// ===========================================================================
// Row softmax (scale then softmax), fp32 in -> bf16 out
// ===========================================================================
__global__ __launch_bounds__(256)
void softmax_rows(const float* __restrict__ S, __nv_bfloat16* __restrict__ O,
                  float scale)
{
    __shared__ float red[256];
    const int tid = threadIdx.x;
    const float* p = S + (long long)blockIdx.x * N_;
    __nv_bfloat16* o = O + (long long)blockIdx.x * N_;

    float vals[8];
    float m = -1e30f;
    #pragma unroll
    for (int i = 0; i < 8; ++i) {
        vals[i] = p[tid + 256 * i] * scale;
        m = fmaxf(m, vals[i]);
    }
    red[tid] = m;
    __syncthreads();
    #pragma unroll
    for (int s = 128; s > 0; s >>= 1) {
        if (tid < s) red[tid] = fmaxf(red[tid], red[tid + s]);
        __syncthreads();
    }
    m = red[0];
    __syncthreads();

    float sum = 0.0f;
    #pragma unroll
    for (int i = 0; i < 8; ++i) {
        vals[i] = __expf(vals[i] - m);
        sum += vals[i];
    }
    red[tid] = sum;
    __syncthreads();
    #pragma unroll
    for (int s = 128; s > 0; s >>= 1) {
        if (tid < s) red[tid] += red[tid + s];
        __syncthreads();
    }
    const float inv = 1.0f / red[0];
    #pragma unroll
    for (int i = 0; i < 8; ++i)
        o[tid + 256 * i] = __float2bfloat16(vals[i] * inv);
}

// ===========================================================================
// adj fp32 [b][k][n] (RxC = N_xN_) -> adjT bf16 [b][n][k]
// ===========================================================================
__global__ __launch_bounds__(256)
void transpose_bf16(const float* __restrict__ A, __nv_bfloat16* __restrict__ T)
{
    __shared__ float t[32][33];
    const int b  = blockIdx.z;
    const int x0 = blockIdx.x * 32;
    const int y0 = blockIdx.y * 32;
    const float* Ab = A + (size_t)b * N_ * N_;
    __nv_bfloat16* Tb = T + (size_t)b * N_ * N_;
    const int tx = threadIdx.x & 31;
    const int ty = threadIdx.x >> 5;
    #pragma unroll
    for (int j = 0; j < 4; ++j)
        t[ty + 8 * j][tx] = Ab[(size_t)(y0 + ty + 8 * j) * N_ + x0 + tx];
    __syncthreads();
    #pragma unroll
    for (int j = 0; j < 4; ++j)
        Tb[(size_t)(x0 + ty + 8 * j) * N_ + y0 + tx] =
            __float2bfloat16(t[tx][ty + 8 * j]);
}

// ===========================================================================
// v fp32 [b][n][d] (N_ x D_) -> vT hi/lo bf16 [b][d][n] (double-bf16 split)
// ===========================================================================
__global__ __launch_bounds__(256)
void transpose_split(const float* __restrict__ A,
                     __nv_bfloat16* __restrict__ Thi,
                     __nv_bfloat16* __restrict__ Tlo)
{
    __shared__ float t[32][33];
    const int b  = blockIdx.z;
    const int x0 = blockIdx.x * 32;    // d
    const int y0 = blockIdx.y * 32;    // n
    const float* Ab = A + (size_t)b * N_ * D_;
    __nv_bfloat16* Hb = Thi + (size_t)b * D_ * N_;
    __nv_bfloat16* Lb = Tlo + (size_t)b * D_ * N_;
    const int tx = threadIdx.x & 31;
    const int ty = threadIdx.x >> 5;
    #pragma unroll
    for (int j = 0; j < 4; ++j)
        t[ty + 8 * j][tx] = Ab[(size_t)(y0 + ty + 8 * j) * D_ + x0 + tx];
    __syncthreads();
    #pragma unroll
    for (int j = 0; j < 4; ++j) {
        float val = t[tx][ty + 8 * j];
        __nv_bfloat16 hi = __float2bfloat16(val);
        __nv_bfloat16 lo = __float2bfloat16(val - __bfloat162float(hi));
        const size_t off = (size_t)(x0 + ty + 8 * j) * N_ + y0 + tx;
        Hb[off] = hi;
        Lb[off] = lo;
    }
}

// ===========================================================================
extern "C" void kernel_launch(void* const* d_in, const int* in_sizes, int n_in,
                              void* d_out, int out_size)
{
    const float* text = (const float*)d_in[0];
    const float* adj  = (const float*)d_in[1];
    const float* Wq   = (const float*)d_in[2];
    const float* bq   = (const float*)d_in[3];
    const float* Wk   = (const float*)d_in[4];
    const float* bk   = (const float*)d_in[5];
    const float* Wv   = (const float*)d_in[6];
    const float* bv   = (const float*)d_in[7];

    float* out     = (float*)d_out;
    float* new_adj = out + (long long)B_ * N_ * D_;

    float *pv, *ps;
    __nv_bfloat16 *pqb, *pkb, *pvth, *pvtl, *pattn, *padjT;
    cudaGetSymbolAddress((void**)&pqb,  g_qb);
    cudaGetSymbolAddress((void**)&pkb,  g_kb);
    cudaGetSymbolAddress((void**)&pv,   g_v);
    cudaGetSymbolAddress((void**)&ps,   g_s);
    cudaGetSymbolAddress((void**)&pvth, g_vth);
    cudaGetSymbolAddress((void**)&pvtl, g_vtl);
    cudaGetSymbolAddress((void**)&pattn, g_attn);
    cudaGetSymbolAddress((void**)&padjT, g_adjT);

    // new_adj hi/lo split aliases the (dead after softmax) scores buffer
    __nv_bfloat16* pnah = (__nv_bfloat16*)ps;
    __nv_bfloat16* pnal = pnah + (size_t)B_ * N_ * N_;

    cudaFuncSetAttribute(hmma_nt<0>,
                         cudaFuncAttributeMaxDynamicSharedMemorySize, SMEM_HMMA);
    cudaFuncSetAttribute(hmma_nt<1>,
                         cudaFuncAttributeMaxDynamicSharedMemorySize, SMEM_HMMA);
    cudaFuncSetAttribute(hmma_out3,
                         cudaFuncAttributeMaxDynamicSharedMemorySize, SMEM_OUT);

    const dim3 t(256);
    const long long sQ = (long long)N_ * D_;
    const long long sS = (long long)N_ * N_;

    // Pass 1: projections — q,k straight to bf16; v stays fp32 (split source)
    {
        dim3 g(D_ / BN, (B_ * N_) / BM, 1);
        gemm_proj<__nv_bfloat16><<<g, t>>>(text, Wq, pqb, bq, B_ * N_, D_, D_);
        gemm_proj<__nv_bfloat16><<<g, t>>>(text, Wk, pkb, bk, B_ * N_, D_, D_);
        gemm_proj<float><<<g, t>>>(text, Wv, pv, bv, B_ * N_, D_, D_);
    }

    // Pass 1b/1c: transposes (adj is independent of pass 1)
    {
        dim3 g(N_ / 32, N_ / 32, B_);
        transpose_bf16<<<g, t>>>(adj, padjT);
    }
    {
        dim3 g(D_ / 32, N_ / 32, B_);
        transpose_split<<<g, t>>>(pv, pvth, pvtl);
    }

    // Pass 2: S = q @ k^T  (bf16 HMMA, fp32 out)
    {
        dim3 g(N_ / 128, N_ / 128, B_);
        hmma_nt<0><<<g, t, SMEM_HMMA>>>(pqb, pkb, ps, nullptr, nullptr,
                                        D_ / 64, D_, D_, N_, sQ, sQ, sS);
    }

    // Pass 3: attn = softmax(S/16) -> bf16
    softmax_rows<<<B_ * N_, t>>>(ps, pattn, 1.0f / 16.0f);

    // Pass 4: new_adj = attn @ adjT^T (fp32 out + hi/lo bf16 split)
    {
        dim3 g(N_ / 128, N_ / 128, B_);
        hmma_nt<1><<<g, t, SMEM_HMMA>>>(pattn, padjT, new_adj, pnah, pnal,
                                        N_ / 64, N_, N_, N_, sS, sS, sS);
    }

    // Pass 5: out = (nah+nal) @ (vth+vtl)^T   (double-bf16, 3-term)
    {
        dim3 g(D_ / 128, N_ / 128, B_);
        hmma_out3<<<g, t, SMEM_OUT>>>(pnah, pnal, pvth, pvtl, out);
    }
}

// round 6
// speedup vs baseline: 4.6924x; 1.1007x over previous
#include <cuda_runtime.h>
#include <cuda_bf16.h>
#include <cstdint>

// ---------------------------------------------------------------------------
// AttentionGNN Round 5: R4 with the hmma_g prologue smem-slot bug fixed
// (prologue wrote Bh/Bl into the wrong/colliding slots for TERMS>=2 ->
//  uninitialized smem read as bf16 -> NaN).
//   pre:   texth/textl = split(text); WT hi/lo splits (transposed weights)
//   pass1: q,k = 2-term HMMA proj (bf16 out, bias); v = 3-term (fp32 out, bias)
//   1b:    vT hi/lo = split(transpose(v));  adjT = transpose(adj) bf16
//   pass2: S = q @ k^T          HMMA -> bf16 scores
//   pass3: attn = softmax(S/16) bf16 -> bf16
//   pass4: new_adj = attn @ adjT^T   HMMA 128x256 tile, fp32 + hi/lo split out
//   pass5: out = Ah@Bh + Al@Bh + Ah@Bl  (double-bf16 3-term HMMA)
// ---------------------------------------------------------------------------

#define B_   8
#define N_   2048
#define D_   256

typedef __nv_bfloat16 bf16;

// Scratch (device globals)
__device__ bf16  g_texth[(size_t)B_ * N_ * D_];
__device__ bf16  g_textl[(size_t)B_ * N_ * D_];
__device__ bf16  g_wth[3 * D_ * D_];          // WqT,WkT,WvT hi
__device__ bf16  g_wtl[3 * D_ * D_];          // lo
__device__ bf16  g_qb [(size_t)B_ * N_ * D_];
__device__ bf16  g_kb [(size_t)B_ * N_ * D_];
__device__ float g_v  [(size_t)B_ * N_ * D_];
__device__ bf16  g_vth[(size_t)B_ * D_ * N_];
__device__ bf16  g_vtl[(size_t)B_ * D_ * N_];
__device__ float g_s  [(size_t)B_ * N_ * N_];   // bf16 scores, then new_adj hi/lo
__device__ bf16  g_attn[(size_t)B_ * N_ * N_];
__device__ bf16  g_adjT[(size_t)B_ * N_ * N_];

// ===========================================================================
// helpers
// ===========================================================================
__device__ __forceinline__ uint32_t smem_u32(const void* p) {
    uint32_t a;
    asm("{ .reg .u64 t; cvta.to.shared.u64 t, %1; cvt.u32.u64 %0, t; }"
        : "=r"(a) : "l"(p));
    return a;
}

#define SMEM_SWIZZLE_128B(off) ((off) ^ (((off) >> 3) & 0x70))

#define CP_ASYNC_16(dst, src) \
    asm volatile("cp.async.cg.shared.global [%0], [%1], 16;" \
                 :: "r"(dst), "l"(src) : "memory")
#define CP_ASYNC_COMMIT() asm volatile("cp.async.commit_group;" ::: "memory")
#define CP_ASYNC_WAIT_ALL() asm volatile("cp.async.wait_group 0;" ::: "memory")

#define LDMATRIX_X4(r0, r1, r2, r3, addr) \
    asm volatile("ldmatrix.sync.aligned.m8n8.x4.shared.b16 {%0,%1,%2,%3}, [%4];" \
                 : "=r"(r0), "=r"(r1), "=r"(r2), "=r"(r3) : "r"(addr))

#define MMA_BF16(d, a, b) \
    asm volatile("mma.sync.aligned.m16n8k16.row.col.f32.bf16.bf16.f32 " \
                 "{%0,%1,%2,%3}, {%4,%5,%6,%7}, {%8,%9}, {%0,%1,%2,%3};" \
                 : "+f"((d)[0]), "+f"((d)[1]), "+f"((d)[2]), "+f"((d)[3]) \
                 : "r"((a)[0]), "r"((a)[1]), "r"((a)[2]), "r"((a)[3]), \
                   "r"((b)[0]), "r"((b)[1]))

#define HTILE 16384

// load ROWS x 64 bf16 tile (128B rows) into SW128 smem via cp.async
template <int ROWS>
__device__ __forceinline__ void load_tileR(
    uint32_t s, const char* gbase, int ldBytes, int tid)
{
    #pragma unroll
    for (int i = 0; i < ROWS / 32; ++i) {
        int id  = tid + 256 * i;
        int row = id >> 3;
        int c   = (id & 7) * 16;
        CP_ASYNC_16(s + SMEM_SWIZZLE_128B(row * 128 + c),
                    gbase + (size_t)row * ldBytes + c);
    }
}

__device__ __forceinline__ void store2(float* p, float a, float b) {
    *(float2*)p = make_float2(a, b);
}
__device__ __forceinline__ void store2(bf16* p, float a, float b) {
    __nv_bfloat162 h;
    h.x = __float2bfloat16(a);
    h.y = __float2bfloat16(b);
    *(__nv_bfloat162*)p = h;
}

// ===========================================================================
// Generic NT HMMA GEMM, CTA 128x128, warps 2(m)x4(n), warp tile 64x32.
//   TERMS=1: Ah@Bh   TERMS=2: +Al@Bh   TERMS=3: +Ah@Bl
// Smem slot layout (single source of truth, used by prologue+mainloop+prefetch):
//   TERMS==1: [Ah, Bh]            TPB=2
//   TERMS==2: [Ah, Al, Bh]        TPB=3
//   TERMS==3: [Ah, Al, Bh, Bl]    TPB=4
// ===========================================================================
template <int TERMS, int BIAS, typename OutT>
__global__ void __launch_bounds__(256, TERMS == 1 ? 2 : 1)
hmma_g(const bf16* __restrict__ Ah, const bf16* __restrict__ Al,
       const bf16* __restrict__ Bh, const bf16* __restrict__ Bl,
       const float* __restrict__ bias, OutT* __restrict__ C,
       int kIters, int ldA, int ldB, int ldC,
       long long sA, long long sB, long long sC)
{
    extern __shared__ char dsm[];
    const uint32_t base = (smem_u32(dsm) + 1023) & ~1023u;
    constexpr int TPB = (TERMS == 1) ? 2 : (TERMS == 2 ? 3 : 4);
    constexpr uint32_t OAL = HTILE;                                  // Al slot
    constexpr uint32_t OBH = (TERMS == 1) ? HTILE : 2u * HTILE;      // Bh slot
    constexpr uint32_t OBL = 3u * HTILE;                             // Bl slot

    const int tid  = threadIdx.x;
    const int lane = tid & 31;
    const int wid  = tid >> 5;
    const int wm0  = (wid & 1) * 64;
    const int wn0  = (wid >> 1) * 32;
    const int lr   = lane & 15;
    const int lc   = lane >> 4;

    const int b  = blockIdx.z;
    const int m0 = blockIdx.y * 128;
    const int n0 = blockIdx.x * 128;
    const char* Ahb = (const char*)(Ah + (size_t)b * sA + (size_t)m0 * ldA);
    const char* Alb = (TERMS >= 2)
        ? (const char*)(Al + (size_t)b * sA + (size_t)m0 * ldA) : nullptr;
    const char* Bhb = (const char*)(Bh + (size_t)b * sB + (size_t)n0 * ldB);
    const char* Blb = (TERMS == 3)
        ? (const char*)(Bl + (size_t)b * sB + (size_t)n0 * ldB) : nullptr;
    const int ldAB = ldA * 2;
    const int ldBB = ldB * 2;

    float acc[4][4][4];
    #pragma unroll
    for (int i = 0; i < 4; ++i)
        #pragma unroll
        for (int j = 0; j < 4; ++j)
            #pragma unroll
            for (int r = 0; r < 4; ++r) acc[i][j][r] = 0.0f;

    // prologue (slots identical to mainloop)
    load_tileR<128>(base, Ahb, ldAB, tid);
    if (TERMS >= 2) load_tileR<128>(base + OAL, Alb, ldAB, tid);
    load_tileR<128>(base + OBH, Bhb, ldBB, tid);
    if (TERMS == 3) load_tileR<128>(base + OBL, Blb, ldBB, tid);
    CP_ASYNC_COMMIT();
    CP_ASYNC_WAIT_ALL();
    __syncthreads();

    for (int kt = 0; kt < kIters; ++kt) {
        const int buf = kt & 1;
        const uint32_t cAh = base + buf * (TPB * HTILE);
        const uint32_t cAl = cAh + OAL;
        const uint32_t cBh = cAh + OBH;
        const uint32_t cBl = cAh + OBL;

        if (kt + 1 < kIters) {
            const uint32_t nx = base + (buf ^ 1) * (TPB * HTILE);
            const size_t ko = (size_t)(kt + 1) * 128;
            load_tileR<128>(nx, Ahb + ko, ldAB, tid);
            if (TERMS >= 2) load_tileR<128>(nx + OAL, Alb + ko, ldAB, tid);
            load_tileR<128>(nx + OBH, Bhb + ko, ldBB, tid);
            if (TERMS == 3) load_tileR<128>(nx + OBL, Blb + ko, ldBB, tid);
            CP_ASYNC_COMMIT();
        }

        #pragma unroll
        for (int ks = 0; ks < 4; ++ks) {
            uint32_t afh[4][4], afl[4][4];
            uint32_t bfh[4][2], bfl[4][2];
            const int csel = ks * 2 + lc;

            #pragma unroll
            for (int mi = 0; mi < 4; ++mi) {
                const int row = wm0 + mi * 16 + lr;
                const uint32_t so = SMEM_SWIZZLE_128B(row * 128 + csel * 16);
                LDMATRIX_X4(afh[mi][0], afh[mi][1], afh[mi][2], afh[mi][3], cAh + so);
                if (TERMS >= 2)
                    LDMATRIX_X4(afl[mi][0], afl[mi][1], afl[mi][2], afl[mi][3], cAl + so);
            }
            #pragma unroll
            for (int nb = 0; nb < 2; ++nb) {
                const int row = wn0 + nb * 16 + lr;
                const uint32_t so = SMEM_SWIZZLE_128B(row * 128 + csel * 16);
                uint32_t r0, r1, r2, r3;
                LDMATRIX_X4(r0, r1, r2, r3, cBh + so);
                bfh[nb * 2][0]     = r0;  bfh[nb * 2][1]     = r2;
                bfh[nb * 2 + 1][0] = r1;  bfh[nb * 2 + 1][1] = r3;
                if (TERMS == 3) {
                    LDMATRIX_X4(r0, r1, r2, r3, cBl + so);
                    bfl[nb * 2][0]     = r0;  bfl[nb * 2][1]     = r2;
                    bfl[nb * 2 + 1][0] = r1;  bfl[nb * 2 + 1][1] = r3;
                }
            }

            #pragma unroll
            for (int mi = 0; mi < 4; ++mi)
                #pragma unroll
                for (int nj = 0; nj < 4; ++nj) {
                    MMA_BF16(acc[mi][nj], afh[mi], bfh[nj]);
                    if (TERMS >= 2) MMA_BF16(acc[mi][nj], afl[mi], bfh[nj]);
                    if (TERMS == 3) MMA_BF16(acc[mi][nj], afh[mi], bfl[nj]);
                }
        }

        CP_ASYNC_WAIT_ALL();
        __syncthreads();
    }

    // epilogue
    const size_t crow = (size_t)b * sC + (size_t)(m0 + wm0) * ldC + n0 + wn0;
    const int r     = lane >> 2;
    const int cpair = (lane & 3) * 2;
    #pragma unroll
    for (int mi = 0; mi < 4; ++mi) {
        #pragma unroll
        for (int nj = 0; nj < 4; ++nj) {
            float v0 = acc[mi][nj][0], v1 = acc[mi][nj][1];
            float v2 = acc[mi][nj][2], v3 = acc[mi][nj][3];
            if (BIAS) {
                const int col = n0 + wn0 + nj * 8 + cpair;
                const float b0 = bias[col], b1 = bias[col + 1];
                v0 += b0; v1 += b1; v2 += b0; v3 += b1;
            }
            const size_t off0 = crow + (size_t)(mi * 16 + r) * ldC + nj * 8 + cpair;
            store2(C + off0, v0, v1);
            store2(C + off0 + (size_t)8 * ldC, v2, v3);
        }
    }
}

// ===========================================================================
// Pass 4: CTA 128(m) x 256(n), warps 2x4, warp tile 64x64, K-chunk 64.
// C = A @ Bt^T, fp32 out + hi/lo bf16 split out.
// ===========================================================================
#define P4_AT 16384
#define P4_BT 32768
#define P4_BUF (P4_AT + P4_BT)
#define SMEM_P4 (2 * P4_BUF + 1024)

__global__ void __launch_bounds__(256)
hmma_p4(const bf16* __restrict__ A, const bf16* __restrict__ Bt,
        float* __restrict__ C, bf16* __restrict__ Chi, bf16* __restrict__ Clo)
{
    extern __shared__ char dsm[];
    const uint32_t base = (smem_u32(dsm) + 1023) & ~1023u;

    const int tid  = threadIdx.x;
    const int lane = tid & 31;
    const int wid  = tid >> 5;
    const int wm0  = (wid & 1) * 64;
    const int wn0  = (wid >> 1) * 64;
    const int lr   = lane & 15;
    const int lc   = lane >> 4;

    const int b  = blockIdx.z;
    const int m0 = blockIdx.y * 128;
    const int n0 = blockIdx.x * 256;
    const char* Ab = (const char*)(A  + ((size_t)b * N_ + m0) * N_);
    const char* Bb = (const char*)(Bt + ((size_t)b * N_ + n0) * N_);
    const int ld = N_ * 2;

    float acc[4][8][4];
    #pragma unroll
    for (int i = 0; i < 4; ++i)
        #pragma unroll
        for (int j = 0; j < 8; ++j)
            #pragma unroll
            for (int r = 0; r < 4; ++r) acc[i][j][r] = 0.0f;

    load_tileR<128>(base,         Ab, ld, tid);
    load_tileR<256>(base + P4_AT, Bb, ld, tid);
    CP_ASYNC_COMMIT();
    CP_ASYNC_WAIT_ALL();
    __syncthreads();

    const int KITER = N_ / 64;   // 32
    for (int kt = 0; kt < KITER; ++kt) {
        const int buf = kt & 1;
        const uint32_t cA = base + buf * P4_BUF;
        const uint32_t cB = cA + P4_AT;

        if (kt + 1 < KITER) {
            const uint32_t nx = base + (buf ^ 1) * P4_BUF;
            const size_t ko = (size_t)(kt + 1) * 128;
            load_tileR<128>(nx,         Ab + ko, ld, tid);
            load_tileR<256>(nx + P4_AT, Bb + ko, ld, tid);
            CP_ASYNC_COMMIT();
        }

        #pragma unroll
        for (int ks = 0; ks < 4; ++ks) {
            uint32_t af[4][4];
            uint32_t bfr[8][2];
            const int csel = ks * 2 + lc;

            #pragma unroll
            for (int mi = 0; mi < 4; ++mi) {
                const int row = wm0 + mi * 16 + lr;
                LDMATRIX_X4(af[mi][0], af[mi][1], af[mi][2], af[mi][3],
                            cA + SMEM_SWIZZLE_128B(row * 128 + csel * 16));
            }
            #pragma unroll
            for (int nb = 0; nb < 4; ++nb) {
                const int row = wn0 + nb * 16 + lr;
                uint32_t r0, r1, r2, r3;
                LDMATRIX_X4(r0, r1, r2, r3,
                            cB + SMEM_SWIZZLE_128B(row * 128 + csel * 16));
                bfr[nb * 2][0]     = r0;  bfr[nb * 2][1]     = r2;
                bfr[nb * 2 + 1][0] = r1;  bfr[nb * 2 + 1][1] = r3;
            }

            #pragma unroll
            for (int mi = 0; mi < 4; ++mi)
                #pragma unroll
                for (int nj = 0; nj < 8; ++nj)
                    MMA_BF16(acc[mi][nj], af[mi], bfr[nj]);
        }

        CP_ASYNC_WAIT_ALL();
        __syncthreads();
    }

    // epilogue: fp32 + hi/lo split
    const size_t crow = ((size_t)b * N_ + m0 + wm0) * N_ + n0 + wn0;
    const int r     = lane >> 2;
    const int cpair = (lane & 3) * 2;
    #pragma unroll
    for (int mi = 0; mi < 4; ++mi) {
        #pragma unroll
        for (int nj = 0; nj < 8; ++nj) {
            const size_t off0 = crow + (size_t)(mi * 16 + r) * N_ + nj * 8 + cpair;
            const size_t off1 = off0 + (size_t)8 * N_;
            *(float2*)(C + off0) = make_float2(acc[mi][nj][0], acc[mi][nj][1]);
            *(float2*)(C + off1) = make_float2(acc[mi][nj][2], acc[mi][nj][3]);
            #pragma unroll
            for (int h = 0; h < 2; ++h) {
                const size_t off = h ? off1 : off0;
                float a0 = acc[mi][nj][h * 2], a1 = acc[mi][nj][h * 2 + 1];
                bf16 h0 = __float2bfloat16(a0);
                bf16 h1 = __float2bfloat16(a1);
                bf16 l0 = __float2bfloat16(a0 - __bfloat162float(h0));
                bf16 l1 = __float2bfloat16(a1 - __bfloat162float(h1));
                __nv_bfloat162 hv; hv.x = h0; hv.y = h1;
                __nv_bfloat162 lv; lv.x = l0; lv.y = l1;
                *(__nv_bfloat162*)(Chi + off) = hv;
                *(__nv_bfloat162*)(Clo + off) = lv;
            }
        }
    }
}

// ===========================================================================
// split fp32 array -> hi/lo bf16 (elementwise, float4 vectorized)
// ===========================================================================
__global__ __launch_bounds__(256)
void split_f32(const float* __restrict__ X, bf16* __restrict__ H,
               bf16* __restrict__ L, size_t n4)
{
    size_t i = (size_t)blockIdx.x * blockDim.x + threadIdx.x;
    if (i >= n4) return;
    float4 v = ((const float4*)X)[i];
    float f[4] = {v.x, v.y, v.z, v.w};
    __nv_bfloat162 hh[2], ll[2];
    #pragma unroll
    for (int j = 0; j < 2; ++j) {
        bf16 h0 = __float2bfloat16(f[2 * j]);
        bf16 h1 = __float2bfloat16(f[2 * j + 1]);
        hh[j].x = h0; hh[j].y = h1;
        ll[j].x = __float2bfloat16(f[2 * j]     - __bfloat162float(h0));
        ll[j].y = __float2bfloat16(f[2 * j + 1] - __bfloat162float(h1));
    }
    ((uint2*)H)[i] = *(uint2*)hh;
    ((uint2*)L)[i] = *(uint2*)ll;
}

// ===========================================================================
// W [256][256] fp32 -> W^T hi/lo bf16 [256][256]
// ===========================================================================
__global__ __launch_bounds__(256)
void wtrans_split(const float* __restrict__ W, bf16* __restrict__ Th,
                  bf16* __restrict__ Tl)
{
    __shared__ float t[32][33];
    const int x0 = blockIdx.x * 32;   // n
    const int y0 = blockIdx.y * 32;   // k
    const int tx = threadIdx.x & 31;
    const int ty = threadIdx.x >> 5;
    #pragma unroll
    for (int j = 0; j < 4; ++j)
        t[ty + 8 * j][tx] = W[(y0 + ty + 8 * j) * D_ + x0 + tx];
    __syncthreads();
    #pragma unroll
    for (int j = 0; j < 4; ++j) {
        float val = t[tx][ty + 8 * j];
        bf16 hi = __float2bfloat16(val);
        const int off = (x0 + ty + 8 * j) * D_ + y0 + tx;
        Th[off] = hi;
        Tl[off] = __float2bfloat16(val - __bfloat162float(hi));
    }
}

// ===========================================================================
// Row softmax, bf16 in -> bf16 out; thread owns 8 contiguous elements.
// ===========================================================================
__global__ __launch_bounds__(256)
void softmax_bf16(const bf16* __restrict__ S, bf16* __restrict__ O, float scale)
{
    __shared__ float red[256];
    const int tid = threadIdx.x;
    const bf16* p = S + (size_t)blockIdx.x * N_ + tid * 8;
    bf16* o       = O + (size_t)blockIdx.x * N_ + tid * 8;

    uint4 raw = *(const uint4*)p;
    __nv_bfloat162* pr = (__nv_bfloat162*)&raw;
    float vals[8];
    float m = -1e30f;
    #pragma unroll
    for (int i = 0; i < 4; ++i) {
        float2 f = __bfloat1622float2(pr[i]);
        vals[2 * i]     = f.x * scale;
        vals[2 * i + 1] = f.y * scale;
        m = fmaxf(m, fmaxf(vals[2 * i], vals[2 * i + 1]));
    }
    red[tid] = m;
    __syncthreads();
    #pragma unroll
    for (int s = 128; s > 0; s >>= 1) {
        if (tid < s) red[tid] = fmaxf(red[tid], red[tid + s]);
        __syncthreads();
    }
    m = red[0];
    __syncthreads();

    float sum = 0.0f;
    #pragma unroll
    for (int i = 0; i < 8; ++i) {
        vals[i] = __expf(vals[i] - m);
        sum += vals[i];
    }
    red[tid] = sum;
    __syncthreads();
    #pragma unroll
    for (int s = 128; s > 0; s >>= 1) {
        if (tid < s) red[tid] += red[tid + s];
        __syncthreads();
    }
    const float inv = 1.0f / red[0];

    uint4 out;
    __nv_bfloat162* po = (__nv_bfloat162*)&out;
    #pragma unroll
    for (int i = 0; i < 4; ++i) {
        po[i].x = __float2bfloat16(vals[2 * i] * inv);
        po[i].y = __float2bfloat16(vals[2 * i + 1] * inv);
    }
    *(uint4*)o = out;
}

// ===========================================================================
// adj fp32 [b][k][n] -> adjT bf16 [b][n][k]
// ===========================================================================
__global__ __launch_bounds__(256)
void transpose_bf16(const float* __restrict__ A, bf16* __restrict__ T)
{
    __shared__ float t[32][33];
    const int b  = blockIdx.z;
    const int x0 = blockIdx.x * 32;
    const int y0 = blockIdx.y * 32;
    const float* Ab = A + (size_t)b * N_ * N_;
    bf16* Tb = T + (size_t)b * N_ * N_;
    const int tx = threadIdx.x & 31;
    const int ty = threadIdx.x >> 5;
    #pragma unroll
    for (int j = 0; j < 4; ++j)
        t[ty + 8 * j][tx] = Ab[(size_t)(y0 + ty + 8 * j) * N_ + x0 + tx];
    __syncthreads();
    #pragma unroll
    for (int j = 0; j < 4; ++j)
        Tb[(size_t)(x0 + ty + 8 * j) * N_ + y0 + tx] =
            __float2bfloat16(t[tx][ty + 8 * j]);
}

// ===========================================================================
// v fp32 [b][n][d] -> vT hi/lo bf16 [b][d][n]
// ===========================================================================
__global__ __launch_bounds__(256)
void transpose_split(const float* __restrict__ A, bf16* __restrict__ Thi,
                     bf16* __restrict__ Tlo)
{
    __shared__ float t[32][33];
    const int b  = blockIdx.z;
    const int x0 = blockIdx.x * 32;    // d
    const int y0 = blockIdx.y * 32;    // n
    const float* Ab = A + (size_t)b * N_ * D_;
    bf16* Hb = Thi + (size_t)b * D_ * N_;
    bf16* Lb = Tlo + (size_t)b * D_ * N_;
    const int tx = threadIdx.x & 31;
    const int ty = threadIdx.x >> 5;
    #pragma unroll
    for (int j = 0; j < 4; ++j)
        t[ty + 8 * j][tx] = Ab[(size_t)(y0 + ty + 8 * j) * D_ + x0 + tx];
    __syncthreads();
    #pragma unroll
    for (int j = 0; j < 4; ++j) {
        float val = t[tx][ty + 8 * j];
        bf16 hi = __float2bfloat16(val);
        const size_t off = (size_t)(x0 + ty + 8 * j) * N_ + y0 + tx;
        Hb[off] = hi;
        Lb[off] = __float2bfloat16(val - __bfloat162float(hi));
    }
}

// ===========================================================================
extern "C" void kernel_launch(void* const* d_in, const int* in_sizes, int n_in,
                              void* d_out, int out_size)
{
    const float* text = (const float*)d_in[0];
    const float* adj  = (const float*)d_in[1];
    const float* Wq   = (const float*)d_in[2];
    const float* bq   = (const float*)d_in[3];
    const float* Wk   = (const float*)d_in[4];
    const float* bk   = (const float*)d_in[5];
    const float* Wv   = (const float*)d_in[6];
    const float* bv   = (const float*)d_in[7];

    float* out     = (float*)d_out;
    float* new_adj = out + (long long)B_ * N_ * D_;

    bf16 *pth, *ptl, *pwth, *pwtl, *pqb, *pkb, *pvth, *pvtl, *pattn, *padjT;
    float *pv, *ps;
    cudaGetSymbolAddress((void**)&pth,  g_texth);
    cudaGetSymbolAddress((void**)&ptl,  g_textl);
    cudaGetSymbolAddress((void**)&pwth, g_wth);
    cudaGetSymbolAddress((void**)&pwtl, g_wtl);
    cudaGetSymbolAddress((void**)&pqb,  g_qb);
    cudaGetSymbolAddress((void**)&pkb,  g_kb);
    cudaGetSymbolAddress((void**)&pv,   g_v);
    cudaGetSymbolAddress((void**)&ps,   g_s);
    cudaGetSymbolAddress((void**)&pvth, g_vth);
    cudaGetSymbolAddress((void**)&pvtl, g_vtl);
    cudaGetSymbolAddress((void**)&pattn, g_attn);
    cudaGetSymbolAddress((void**)&padjT, g_adjT);

    bf16* psb  = (bf16*)ps;                       // bf16 scores alias
    bf16* pnah = (bf16*)ps;                       // new_adj hi (scores dead)
    bf16* pnal = pnah + (size_t)B_ * N_ * N_;     // new_adj lo

    const int SMEM_G1 = 2 * 2 * HTILE + 1024;
    const int SMEM_G2 = 2 * 3 * HTILE + 1024;
    const int SMEM_G3 = 2 * 4 * HTILE + 1024;
    cudaFuncSetAttribute((const void*)hmma_g<1, 0, bf16>,
                         cudaFuncAttributeMaxDynamicSharedMemorySize, SMEM_G1);
    cudaFuncSetAttribute((const void*)hmma_g<2, 1, bf16>,
                         cudaFuncAttributeMaxDynamicSharedMemorySize, SMEM_G2);
    cudaFuncSetAttribute((const void*)hmma_g<3, 1, float>,
                         cudaFuncAttributeMaxDynamicSharedMemorySize, SMEM_G3);
    cudaFuncSetAttribute((const void*)hmma_g<3, 0, float>,
                         cudaFuncAttributeMaxDynamicSharedMemorySize, SMEM_G3);
    cudaFuncSetAttribute((const void*)hmma_p4,
                         cudaFuncAttributeMaxDynamicSharedMemorySize, SMEM_P4);

    const dim3 t(256);
    const long long sQ = (long long)N_ * D_;
    const long long sS = (long long)N_ * N_;

    // pre: split text; transpose+split weights
    {
        const size_t n4 = (size_t)B_ * N_ * D_ / 4;
        split_f32<<<(unsigned)((n4 + 255) / 256), t>>>(text, pth, ptl, n4);
        dim3 g(D_ / 32, D_ / 32, 1);
        wtrans_split<<<g, t>>>(Wq, pwth,               pwtl);
        wtrans_split<<<g, t>>>(Wk, pwth + D_ * D_,     pwtl + D_ * D_);
        wtrans_split<<<g, t>>>(Wv, pwth + 2 * D_ * D_, pwtl + 2 * D_ * D_);
    }

    // adjT (independent)
    {
        dim3 g(N_ / 32, N_ / 32, B_);
        transpose_bf16<<<g, t>>>(adj, padjT);
    }

    // pass 1: projections via HMMA
    {
        dim3 g(D_ / 128, (B_ * N_) / 128, 1);   // (2, 128, 1)
        hmma_g<2, 1, bf16><<<g, t, SMEM_G2>>>(
            pth, ptl, pwth, nullptr, bq, pqb, D_ / 64, D_, D_, D_, 0, 0, 0);
        hmma_g<2, 1, bf16><<<g, t, SMEM_G2>>>(
            pth, ptl, pwth + D_ * D_, nullptr, bk, pkb, D_ / 64, D_, D_, D_, 0, 0, 0);
        hmma_g<3, 1, float><<<g, t, SMEM_G3>>>(
            pth, ptl, pwth + 2 * D_ * D_, pwtl + 2 * D_ * D_, bv, pv,
            D_ / 64, D_, D_, D_, 0, 0, 0);
    }

    // v^T split
    {
        dim3 g(D_ / 32, N_ / 32, B_);
        transpose_split<<<g, t>>>(pv, pvth, pvtl);
    }

    // pass 2: S = q @ k^T -> bf16
    {
        dim3 g(N_ / 128, N_ / 128, B_);
        hmma_g<1, 0, bf16><<<g, t, SMEM_G1>>>(
            pqb, nullptr, pkb, nullptr, nullptr, psb,
            D_ / 64, D_, D_, N_, sQ, sQ, sS);
    }

    // pass 3: softmax
    softmax_bf16<<<B_ * N_, t>>>(psb, pattn, 1.0f / 16.0f);

    // pass 4: new_adj = attn @ adjT^T  (128x256 tile, fp32 + split out)
    {
        dim3 g(N_ / 256, N_ / 128, B_);   // (8, 16, 8)
        hmma_p4<<<g, t, SMEM_P4>>>(pattn, padjT, new_adj, pnah, pnal);
    }

    // pass 5: out = Ah@Bh + Al@Bh + Ah@Bl
    {
        dim3 g(D_ / 128, N_ / 128, B_);   // (2, 16, 8)
        hmma_g<3, 0, float><<<g, t, SMEM_G3>>>(
            pnah, pnal, pvth, pvtl, nullptr, out,
            N_ / 64, N_, N_, D_, sS, (long long)D_ * N_, sQ);
    }
}

// round 7
// speedup vs baseline: 4.8182x; 1.0268x over previous
#include <cuda_runtime.h>
#include <cuda_bf16.h>
#include <cstdint>

// ---------------------------------------------------------------------------
// AttentionGNN Round 6:
//   - pass4: 3-stage cp.async pipeline (wait_group 1), fp32-only epilogue
//   - pass5: reads fp32 new_adj, double-bf16 split done in-kernel (regs->STS)
//   otherwise identical to Round 5.
// ---------------------------------------------------------------------------

#define B_   8
#define N_   2048
#define D_   256

typedef __nv_bfloat16 bf16;

// Scratch (device globals)
__device__ bf16  g_texth[(size_t)B_ * N_ * D_];
__device__ bf16  g_textl[(size_t)B_ * N_ * D_];
__device__ bf16  g_wth[3 * D_ * D_];
__device__ bf16  g_wtl[3 * D_ * D_];
__device__ bf16  g_qb [(size_t)B_ * N_ * D_];
__device__ bf16  g_kb [(size_t)B_ * N_ * D_];
__device__ float g_v  [(size_t)B_ * N_ * D_];
__device__ bf16  g_vth[(size_t)B_ * D_ * N_];
__device__ bf16  g_vtl[(size_t)B_ * D_ * N_];
__device__ float g_s  [(size_t)B_ * N_ * N_];   // fp32-sized; bf16 scores alias
__device__ bf16  g_attn[(size_t)B_ * N_ * N_];
__device__ bf16  g_adjT[(size_t)B_ * N_ * N_];

// ===========================================================================
// helpers
// ===========================================================================
__device__ __forceinline__ uint32_t smem_u32(const void* p) {
    uint32_t a;
    asm("{ .reg .u64 t; cvta.to.shared.u64 t, %1; cvt.u32.u64 %0, t; }"
        : "=r"(a) : "l"(p));
    return a;
}

#define SMEM_SWIZZLE_128B(off) ((off) ^ (((off) >> 3) & 0x70))

#define CP_ASYNC_16(dst, src) \
    asm volatile("cp.async.cg.shared.global [%0], [%1], 16;" \
                 :: "r"(dst), "l"(src) : "memory")
#define CP_ASYNC_COMMIT() asm volatile("cp.async.commit_group;" ::: "memory")
#define CP_ASYNC_WAIT_ALL() asm volatile("cp.async.wait_group 0;" ::: "memory")
#define CP_ASYNC_WAIT_1()  asm volatile("cp.async.wait_group 1;" ::: "memory")

#define LDMATRIX_X4(r0, r1, r2, r3, addr) \
    asm volatile("ldmatrix.sync.aligned.m8n8.x4.shared.b16 {%0,%1,%2,%3}, [%4];" \
                 : "=r"(r0), "=r"(r1), "=r"(r2), "=r"(r3) : "r"(addr))

#define MMA_BF16(d, a, b) \
    asm volatile("mma.sync.aligned.m16n8k16.row.col.f32.bf16.bf16.f32 " \
                 "{%0,%1,%2,%3}, {%4,%5,%6,%7}, {%8,%9}, {%0,%1,%2,%3};" \
                 : "+f"((d)[0]), "+f"((d)[1]), "+f"((d)[2]), "+f"((d)[3]) \
                 : "r"((a)[0]), "r"((a)[1]), "r"((a)[2]), "r"((a)[3]), \
                   "r"((b)[0]), "r"((b)[1]))

#define HTILE 16384

// load ROWS x 64 bf16 tile (128B rows) into SW128 smem via cp.async
template <int ROWS>
__device__ __forceinline__ void load_tileR(
    uint32_t s, const char* gbase, int ldBytes, int tid)
{
    #pragma unroll
    for (int i = 0; i < ROWS / 32; ++i) {
        int id  = tid + 256 * i;
        int row = id >> 3;
        int c   = (id & 7) * 16;
        CP_ASYNC_16(s + SMEM_SWIZZLE_128B(row * 128 + c),
                    gbase + (size_t)row * ldBytes + c);
    }
}

__device__ __forceinline__ void store2(float* p, float a, float b) {
    *(float2*)p = make_float2(a, b);
}
__device__ __forceinline__ void store2(bf16* p, float a, float b) {
    __nv_bfloat162 h;
    h.x = __float2bfloat16(a);
    h.y = __float2bfloat16(b);
    *(__nv_bfloat162*)p = h;
}

// ===========================================================================
// Generic NT HMMA GEMM, CTA 128x128, warps 2(m)x4(n), warp tile 64x32.
//   TERMS=1: Ah@Bh   TERMS=2: +Al@Bh   TERMS=3: +Ah@Bl
// Slot layout: TERMS==1 [Ah,Bh]; TERMS==2 [Ah,Al,Bh]; TERMS==3 [Ah,Al,Bh,Bl]
// ===========================================================================
template <int TERMS, int BIAS, typename OutT>
__global__ void __launch_bounds__(256, TERMS == 1 ? 2 : 1)
hmma_g(const bf16* __restrict__ Ah, const bf16* __restrict__ Al,
       const bf16* __restrict__ Bh, const bf16* __restrict__ Bl,
       const float* __restrict__ bias, OutT* __restrict__ C,
       int kIters, int ldA, int ldB, int ldC,
       long long sA, long long sB, long long sC)
{
    extern __shared__ char dsm[];
    const uint32_t base = (smem_u32(dsm) + 1023) & ~1023u;
    constexpr int TPB = (TERMS == 1) ? 2 : (TERMS == 2 ? 3 : 4);
    constexpr uint32_t OAL = HTILE;
    constexpr uint32_t OBH = (TERMS == 1) ? HTILE : 2u * HTILE;
    constexpr uint32_t OBL = 3u * HTILE;

    const int tid  = threadIdx.x;
    const int lane = tid & 31;
    const int wid  = tid >> 5;
    const int wm0  = (wid & 1) * 64;
    const int wn0  = (wid >> 1) * 32;
    const int lr   = lane & 15;
    const int lc   = lane >> 4;

    const int b  = blockIdx.z;
    const int m0 = blockIdx.y * 128;
    const int n0 = blockIdx.x * 128;
    const char* Ahb = (const char*)(Ah + (size_t)b * sA + (size_t)m0 * ldA);
    const char* Alb = (TERMS >= 2)
        ? (const char*)(Al + (size_t)b * sA + (size_t)m0 * ldA) : nullptr;
    const char* Bhb = (const char*)(Bh + (size_t)b * sB + (size_t)n0 * ldB);
    const char* Blb = (TERMS == 3)
        ? (const char*)(Bl + (size_t)b * sB + (size_t)n0 * ldB) : nullptr;
    const int ldAB = ldA * 2;
    const int ldBB = ldB * 2;

    float acc[4][4][4];
    #pragma unroll
    for (int i = 0; i < 4; ++i)
        #pragma unroll
        for (int j = 0; j < 4; ++j)
            #pragma unroll
            for (int r = 0; r < 4; ++r) acc[i][j][r] = 0.0f;

    load_tileR<128>(base, Ahb, ldAB, tid);
    if (TERMS >= 2) load_tileR<128>(base + OAL, Alb, ldAB, tid);
    load_tileR<128>(base + OBH, Bhb, ldBB, tid);
    if (TERMS == 3) load_tileR<128>(base + OBL, Blb, ldBB, tid);
    CP_ASYNC_COMMIT();
    CP_ASYNC_WAIT_ALL();
    __syncthreads();

    for (int kt = 0; kt < kIters; ++kt) {
        const int buf = kt & 1;
        const uint32_t cAh = base + buf * (TPB * HTILE);
        const uint32_t cAl = cAh + OAL;
        const uint32_t cBh = cAh + OBH;
        const uint32_t cBl = cAh + OBL;

        if (kt + 1 < kIters) {
            const uint32_t nx = base + (buf ^ 1) * (TPB * HTILE);
            const size_t ko = (size_t)(kt + 1) * 128;
            load_tileR<128>(nx, Ahb + ko, ldAB, tid);
            if (TERMS >= 2) load_tileR<128>(nx + OAL, Alb + ko, ldAB, tid);
            load_tileR<128>(nx + OBH, Bhb + ko, ldBB, tid);
            if (TERMS == 3) load_tileR<128>(nx + OBL, Blb + ko, ldBB, tid);
            CP_ASYNC_COMMIT();
        }

        #pragma unroll
        for (int ks = 0; ks < 4; ++ks) {
            uint32_t afh[4][4], afl[4][4];
            uint32_t bfh[4][2], bfl[4][2];
            const int csel = ks * 2 + lc;

            #pragma unroll
            for (int mi = 0; mi < 4; ++mi) {
                const int row = wm0 + mi * 16 + lr;
                const uint32_t so = SMEM_SWIZZLE_128B(row * 128 + csel * 16);
                LDMATRIX_X4(afh[mi][0], afh[mi][1], afh[mi][2], afh[mi][3], cAh + so);
                if (TERMS >= 2)
                    LDMATRIX_X4(afl[mi][0], afl[mi][1], afl[mi][2], afl[mi][3], cAl + so);
            }
            #pragma unroll
            for (int nb = 0; nb < 2; ++nb) {
                const int row = wn0 + nb * 16 + lr;
                const uint32_t so = SMEM_SWIZZLE_128B(row * 128 + csel * 16);
                uint32_t r0, r1, r2, r3;
                LDMATRIX_X4(r0, r1, r2, r3, cBh + so);
                bfh[nb * 2][0]     = r0;  bfh[nb * 2][1]     = r2;
                bfh[nb * 2 + 1][0] = r1;  bfh[nb * 2 + 1][1] = r3;
                if (TERMS == 3) {
                    LDMATRIX_X4(r0, r1, r2, r3, cBl + so);
                    bfl[nb * 2][0]     = r0;  bfl[nb * 2][1]     = r2;
                    bfl[nb * 2 + 1][0] = r1;  bfl[nb * 2 + 1][1] = r3;
                }
            }

            #pragma unroll
            for (int mi = 0; mi < 4; ++mi)
                #pragma unroll
                for (int nj = 0; nj < 4; ++nj) {
                    MMA_BF16(acc[mi][nj], afh[mi], bfh[nj]);
                    if (TERMS >= 2) MMA_BF16(acc[mi][nj], afl[mi], bfh[nj]);
                    if (TERMS == 3) MMA_BF16(acc[mi][nj], afh[mi], bfl[nj]);
                }
        }

        CP_ASYNC_WAIT_ALL();
        __syncthreads();
    }

    const size_t crow = (size_t)b * sC + (size_t)(m0 + wm0) * ldC + n0 + wn0;
    const int r     = lane >> 2;
    const int cpair = (lane & 3) * 2;
    #pragma unroll
    for (int mi = 0; mi < 4; ++mi) {
        #pragma unroll
        for (int nj = 0; nj < 4; ++nj) {
            float v0 = acc[mi][nj][0], v1 = acc[mi][nj][1];
            float v2 = acc[mi][nj][2], v3 = acc[mi][nj][3];
            if (BIAS) {
                const int col = n0 + wn0 + nj * 8 + cpair;
                const float b0 = bias[col], b1 = bias[col + 1];
                v0 += b0; v1 += b1; v2 += b0; v3 += b1;
            }
            const size_t off0 = crow + (size_t)(mi * 16 + r) * ldC + nj * 8 + cpair;
            store2(C + off0, v0, v1);
            store2(C + off0 + (size_t)8 * ldC, v2, v3);
        }
    }
}

// ===========================================================================
// Pass 4: CTA 128(m) x 256(n), warps 2x4, warp tile 64x64, K-chunk 64.
// 3-stage cp.async pipeline. fp32-only epilogue.
// ===========================================================================
#define P4_AT 16384
#define P4_BT 32768
#define P4_BUF (P4_AT + P4_BT)
#define SMEM_P4 (3 * P4_BUF + 1024)

__global__ void __launch_bounds__(256)
hmma_p4(const bf16* __restrict__ A, const bf16* __restrict__ Bt,
        float* __restrict__ C)
{
    extern __shared__ char dsm[];
    const uint32_t base = (smem_u32(dsm) + 1023) & ~1023u;

    const int tid  = threadIdx.x;
    const int lane = tid & 31;
    const int wid  = tid >> 5;
    const int wm0  = (wid & 1) * 64;
    const int wn0  = (wid >> 1) * 64;
    const int lr   = lane & 15;
    const int lc   = lane >> 4;

    const int b  = blockIdx.z;
    const int m0 = blockIdx.y * 128;
    const int n0 = blockIdx.x * 256;
    const char* Ab = (const char*)(A  + ((size_t)b * N_ + m0) * N_);
    const char* Bb = (const char*)(Bt + ((size_t)b * N_ + n0) * N_);
    const int ld = N_ * 2;

    float acc[4][8][4];
    #pragma unroll
    for (int i = 0; i < 4; ++i)
        #pragma unroll
        for (int j = 0; j < 8; ++j)
            #pragma unroll
            for (int r = 0; r < 4; ++r) acc[i][j][r] = 0.0f;

    const int KITER = N_ / 64;   // 32

    // prologue: stages 0 and 1 in flight
    load_tileR<128>(base,         Ab, ld, tid);
    load_tileR<256>(base + P4_AT, Bb, ld, tid);
    CP_ASYNC_COMMIT();
    load_tileR<128>(base + P4_BUF,         Ab + 128, ld, tid);
    load_tileR<256>(base + P4_BUF + P4_AT, Bb + 128, ld, tid);
    CP_ASYNC_COMMIT();

    for (int kt = 0; kt < KITER; ++kt) {
        // stage kt must be retired; kt+1 may remain in flight
        if (kt + 1 < KITER) { CP_ASYNC_WAIT_1(); } else { CP_ASYNC_WAIT_ALL(); }
        __syncthreads();   // also guarantees all warps finished compute kt-1

        if (kt + 2 < KITER) {
            const uint32_t nx = base + ((kt + 2) % 3) * P4_BUF;
            const size_t ko = (size_t)(kt + 2) * 128;
            load_tileR<128>(nx,         Ab + ko, ld, tid);
            load_tileR<256>(nx + P4_AT, Bb + ko, ld, tid);
            CP_ASYNC_COMMIT();
        }

        const uint32_t cA = base + (kt % 3) * P4_BUF;
        const uint32_t cB = cA + P4_AT;

        #pragma unroll
        for (int ks = 0; ks < 4; ++ks) {
            uint32_t af[4][4];
            uint32_t bfr[8][2];
            const int csel = ks * 2 + lc;

            #pragma unroll
            for (int mi = 0; mi < 4; ++mi) {
                const int row = wm0 + mi * 16 + lr;
                LDMATRIX_X4(af[mi][0], af[mi][1], af[mi][2], af[mi][3],
                            cA + SMEM_SWIZZLE_128B(row * 128 + csel * 16));
            }
            #pragma unroll
            for (int nb = 0; nb < 4; ++nb) {
                const int row = wn0 + nb * 16 + lr;
                uint32_t r0, r1, r2, r3;
                LDMATRIX_X4(r0, r1, r2, r3,
                            cB + SMEM_SWIZZLE_128B(row * 128 + csel * 16));
                bfr[nb * 2][0]     = r0;  bfr[nb * 2][1]     = r2;
                bfr[nb * 2 + 1][0] = r1;  bfr[nb * 2 + 1][1] = r3;
            }

            #pragma unroll
            for (int mi = 0; mi < 4; ++mi)
                #pragma unroll
                for (int nj = 0; nj < 8; ++nj)
                    MMA_BF16(acc[mi][nj], af[mi], bfr[nj]);
        }
    }

    // epilogue: fp32 only
    const size_t crow = ((size_t)b * N_ + m0 + wm0) * N_ + n0 + wn0;
    const int r     = lane >> 2;
    const int cpair = (lane & 3) * 2;
    #pragma unroll
    for (int mi = 0; mi < 4; ++mi) {
        #pragma unroll
        for (int nj = 0; nj < 8; ++nj) {
            const size_t off0 = crow + (size_t)(mi * 16 + r) * N_ + nj * 8 + cpair;
            *(float2*)(C + off0) = make_float2(acc[mi][nj][0], acc[mi][nj][1]);
            *(float2*)(C + off0 + (size_t)8 * N_) =
                make_float2(acc[mi][nj][2], acc[mi][nj][3]);
        }
    }
}

// ===========================================================================
// Pass 5: out = (Ah+Al) @ (Bh+Bl)^T, 3 terms; A arrives as fp32 (new_adj) and
// is split to hi/lo in-kernel (LDG float4 -> regs -> STS to swizzled smem).
// CTA 128x128, warps 2x4, warp tile 64x32, K-chunk 64.
// Smem/buffer: [Ah, Al, Bh, Bl] x2 = 128 KB.
// ===========================================================================
#define SMEM_P5 (2 * 4 * HTILE + 1024)

__global__ void __launch_bounds__(256)
hmma_out2(const float* __restrict__ A,     // new_adj fp32 [B,N,N]
          const bf16* __restrict__ Bh,     // vT hi [B,D,N]
          const bf16* __restrict__ Bl,     // vT lo [B,D,N]
          float* __restrict__ C)           // out [B,N,D]
{
    extern __shared__ char dsm[];
    const uint32_t base = (smem_u32(dsm) + 1023) & ~1023u;
    char* dbase = dsm + (base - smem_u32(dsm));

    const int tid  = threadIdx.x;
    const int lane = tid & 31;
    const int wid  = tid >> 5;
    const int wm0  = (wid & 1) * 64;
    const int wn0  = (wid >> 1) * 32;
    const int lr   = lane & 15;
    const int lc   = lane >> 4;

    const int b  = blockIdx.z;
    const int m0 = blockIdx.y * 128;
    const int n0 = blockIdx.x * 128;    // d-offset
    const char* Ab  = (const char*)(A  + ((size_t)b * N_ + m0) * N_);
    const char* Bhb = (const char*)(Bh + ((size_t)b * D_ + n0) * N_);
    const char* Blb = (const char*)(Bl + ((size_t)b * D_ + n0) * N_);
    const int ldA = N_ * 4;   // fp32 row bytes
    const int ldB = N_ * 2;

    // per-thread A-load mapping: 8 float4 chunks of the 128x64 fp32 tile
    // id = tid + 256*i : row = id>>4, c16 = id&15 (float4 index within row)
    float4 ar[8];

    auto ldg_A = [&](int kt) {
        #pragma unroll
        for (int i = 0; i < 8; ++i) {
            const int id  = tid + 256 * i;
            const int row = id >> 4;
            const int c16 = id & 15;
            ar[i] = *(const float4*)(Ab + (size_t)row * ldA + (size_t)kt * 256
                                        + c16 * 16);
        }
    };
    auto sts_A = [&](int buf) {
        char* sAh = dbase + buf * (4 * HTILE);
        char* sAl = sAh + HTILE;
        #pragma unroll
        for (int i = 0; i < 8; ++i) {
            const int id  = tid + 256 * i;
            const int row = id >> 4;
            const int c16 = id & 15;
            const uint32_t sw = SMEM_SWIZZLE_128B(row * 128 + c16 * 8);
            const float f[4] = {ar[i].x, ar[i].y, ar[i].z, ar[i].w};
            __nv_bfloat162 hv[2], lv[2];
            #pragma unroll
            for (int j = 0; j < 2; ++j) {
                bf16 h0 = __float2bfloat16(f[2 * j]);
                bf16 h1 = __float2bfloat16(f[2 * j + 1]);
                hv[j].x = h0; hv[j].y = h1;
                lv[j].x = __float2bfloat16(f[2 * j]     - __bfloat162float(h0));
                lv[j].y = __float2bfloat16(f[2 * j + 1] - __bfloat162float(h1));
            }
            *(uint2*)(sAh + sw) = *(uint2*)hv;
            *(uint2*)(sAl + sw) = *(uint2*)lv;
        }
    };

    float acc[4][4][4];
    #pragma unroll
    for (int i = 0; i < 4; ++i)
        #pragma unroll
        for (int j = 0; j < 4; ++j)
            #pragma unroll
            for (int r = 0; r < 4; ++r) acc[i][j][r] = 0.0f;

    // prologue: stage 0
    load_tileR<128>(base + 2 * HTILE, Bhb, ldB, tid);
    load_tileR<128>(base + 3 * HTILE, Blb, ldB, tid);
    CP_ASYNC_COMMIT();
    ldg_A(0);
    sts_A(0);
    CP_ASYNC_WAIT_ALL();
    __syncthreads();

    const int KITER = N_ / 64;   // 32
    for (int kt = 0; kt < KITER; ++kt) {
        const int buf = kt & 1;
        const uint32_t cAh = base + buf * (4 * HTILE);
        const uint32_t cAl = cAh + HTILE;
        const uint32_t cBh = cAh + 2 * HTILE;
        const uint32_t cBl = cAh + 3 * HTILE;

        if (kt + 1 < KITER) {
            const uint32_t nx = base + (buf ^ 1) * (4 * HTILE);
            load_tileR<128>(nx + 2 * HTILE, Bhb + (size_t)(kt + 1) * 128, ldB, tid);
            load_tileR<128>(nx + 3 * HTILE, Blb + (size_t)(kt + 1) * 128, ldB, tid);
            CP_ASYNC_COMMIT();
            ldg_A(kt + 1);    // LDG overlaps compute below
        }

        #pragma unroll
        for (int ks = 0; ks < 4; ++ks) {
            uint32_t afh[4][4], afl[4][4];
            uint32_t bfh[4][2], bfl[4][2];
            const int csel = ks * 2 + lc;

            #pragma unroll
            for (int mi = 0; mi < 4; ++mi) {
                const int row = wm0 + mi * 16 + lr;
                const uint32_t so = SMEM_SWIZZLE_128B(row * 128 + csel * 16);
                LDMATRIX_X4(afh[mi][0], afh[mi][1], afh[mi][2], afh[mi][3], cAh + so);
                LDMATRIX_X4(afl[mi][0], afl[mi][1], afl[mi][2], afl[mi][3], cAl + so);
            }
            #pragma unroll
            for (int nb = 0; nb < 2; ++nb) {
                const int row = wn0 + nb * 16 + lr;
                const uint32_t so = SMEM_SWIZZLE_128B(row * 128 + csel * 16);
                uint32_t r0, r1, r2, r3;
                LDMATRIX_X4(r0, r1, r2, r3, cBh + so);
                bfh[nb * 2][0]     = r0;  bfh[nb * 2][1]     = r2;
                bfh[nb * 2 + 1][0] = r1;  bfh[nb * 2 + 1][1] = r3;
                LDMATRIX_X4(r0, r1, r2, r3, cBl + so);
                bfl[nb * 2][0]     = r0;  bfl[nb * 2][1]     = r2;
                bfl[nb * 2 + 1][0] = r1;  bfl[nb * 2 + 1][1] = r3;
            }

            #pragma unroll
            for (int mi = 0; mi < 4; ++mi)
                #pragma unroll
                for (int nj = 0; nj < 4; ++nj) {
                    MMA_BF16(acc[mi][nj], afh[mi], bfh[nj]);
                    MMA_BF16(acc[mi][nj], afl[mi], bfh[nj]);
                    MMA_BF16(acc[mi][nj], afh[mi], bfl[nj]);
                }
        }

        if (kt + 1 < KITER) {
            __syncthreads();          // all warps done reading buf^1 (iter kt-1)
            sts_A(buf ^ 1);           // write A hi/lo for kt+1
            CP_ASYNC_WAIT_ALL();      // B tiles for kt+1 landed
            __syncthreads();
        }
    }

    float* Cb = C + ((size_t)b * N_ + m0 + wm0) * D_ + n0 + wn0;
    const int r     = lane >> 2;
    const int cpair = (lane & 3) * 2;
    #pragma unroll
    for (int mi = 0; mi < 4; ++mi) {
        #pragma unroll
        for (int nj = 0; nj < 4; ++nj) {
            float* p = Cb + (size_t)(mi * 16 + r) * D_ + nj * 8 + cpair;
            *(float2*)p            = make_float2(acc[mi][nj][0], acc[mi][nj][1]);
            *(float2*)(p + 8 * D_) = make_float2(acc[mi][nj][2], acc[mi][nj][3]);
        }
    }
}

// ===========================================================================
// split fp32 array -> hi/lo bf16 (elementwise, float4 vectorized)
// ===========================================================================
__global__ __launch_bounds__(256)
void split_f32(const float* __restrict__ X, bf16* __restrict__ H,
               bf16* __restrict__ L, size_t n4)
{
    size_t i = (size_t)blockIdx.x * blockDim.x + threadIdx.x;
    if (i >= n4) return;
    float4 v = ((const float4*)X)[i];
    float f[4] = {v.x, v.y, v.z, v.w};
    __nv_bfloat162 hh[2], ll[2];
    #pragma unroll
    for (int j = 0; j < 2; ++j) {
        bf16 h0 = __float2bfloat16(f[2 * j]);
        bf16 h1 = __float2bfloat16(f[2 * j + 1]);
        hh[j].x = h0; hh[j].y = h1;
        ll[j].x = __float2bfloat16(f[2 * j]     - __bfloat162float(h0));
        ll[j].y = __float2bfloat16(f[2 * j + 1] - __bfloat162float(h1));
    }
    ((uint2*)H)[i] = *(uint2*)hh;
    ((uint2*)L)[i] = *(uint2*)ll;
}

// ===========================================================================
// W [256][256] fp32 -> W^T hi/lo bf16
// ===========================================================================
__global__ __launch_bounds__(256)
void wtrans_split(const float* __restrict__ W, bf16* __restrict__ Th,
                  bf16* __restrict__ Tl)
{
    __shared__ float t[32][33];
    const int x0 = blockIdx.x * 32;
    const int y0 = blockIdx.y * 32;
    const int tx = threadIdx.x & 31;
    const int ty = threadIdx.x >> 5;
    #pragma unroll
    for (int j = 0; j < 4; ++j)
        t[ty + 8 * j][tx] = W[(y0 + ty + 8 * j) * D_ + x0 + tx];
    __syncthreads();
    #pragma unroll
    for (int j = 0; j < 4; ++j) {
        float val = t[tx][ty + 8 * j];
        bf16 hi = __float2bfloat16(val);
        const int off = (x0 + ty + 8 * j) * D_ + y0 + tx;
        Th[off] = hi;
        Tl[off] = __float2bfloat16(val - __bfloat162float(hi));
    }
}

// ===========================================================================
// Row softmax, bf16 in -> bf16 out
// ===========================================================================
__global__ __launch_bounds__(256)
void softmax_bf16(const bf16* __restrict__ S, bf16* __restrict__ O, float scale)
{
    __shared__ float red[256];
    const int tid = threadIdx.x;
    const bf16* p = S + (size_t)blockIdx.x * N_ + tid * 8;
    bf16* o       = O + (size_t)blockIdx.x * N_ + tid * 8;

    uint4 raw = *(const uint4*)p;
    __nv_bfloat162* pr = (__nv_bfloat162*)&raw;
    float vals[8];
    float m = -1e30f;
    #pragma unroll
    for (int i = 0; i < 4; ++i) {
        float2 f = __bfloat1622float2(pr[i]);
        vals[2 * i]     = f.x * scale;
        vals[2 * i + 1] = f.y * scale;
        m = fmaxf(m, fmaxf(vals[2 * i], vals[2 * i + 1]));
    }
    red[tid] = m;
    __syncthreads();
    #pragma unroll
    for (int s = 128; s > 0; s >>= 1) {
        if (tid < s) red[tid] = fmaxf(red[tid], red[tid + s]);
        __syncthreads();
    }
    m = red[0];
    __syncthreads();

    float sum = 0.0f;
    #pragma unroll
    for (int i = 0; i < 8; ++i) {
        vals[i] = __expf(vals[i] - m);
        sum += vals[i];
    }
    red[tid] = sum;
    __syncthreads();
    #pragma unroll
    for (int s = 128; s > 0; s >>= 1) {
        if (tid < s) red[tid] += red[tid + s];
        __syncthreads();
    }
    const float inv = 1.0f / red[0];

    uint4 outv;
    __nv_bfloat162* po = (__nv_bfloat162*)&outv;
    #pragma unroll
    for (int i = 0; i < 4; ++i) {
        po[i].x = __float2bfloat16(vals[2 * i] * inv);
        po[i].y = __float2bfloat16(vals[2 * i + 1] * inv);
    }
    *(uint4*)o = outv;
}

// ===========================================================================
// adj fp32 [b][k][n] -> adjT bf16 [b][n][k]
// ===========================================================================
__global__ __launch_bounds__(256)
void transpose_bf16(const float* __restrict__ A, bf16* __restrict__ T)
{
    __shared__ float t[32][33];
    const int b  = blockIdx.z;
    const int x0 = blockIdx.x * 32;
    const int y0 = blockIdx.y * 32;
    const float* Ab = A + (size_t)b * N_ * N_;
    bf16* Tb = T + (size_t)b * N_ * N_;
    const int tx = threadIdx.x & 31;
    const int ty = threadIdx.x >> 5;
    #pragma unroll
    for (int j = 0; j < 4; ++j)
        t[ty + 8 * j][tx] = Ab[(size_t)(y0 + ty + 8 * j) * N_ + x0 + tx];
    __syncthreads();
    #pragma unroll
    for (int j = 0; j < 4; ++j)
        Tb[(size_t)(x0 + ty + 8 * j) * N_ + y0 + tx] =
            __float2bfloat16(t[tx][ty + 8 * j]);
}

// ===========================================================================
// v fp32 [b][n][d] -> vT hi/lo bf16 [b][d][n]
// ===========================================================================
__global__ __launch_bounds__(256)
void transpose_split(const float* __restrict__ A, bf16* __restrict__ Thi,
                     bf16* __restrict__ Tlo)
{
    __shared__ float t[32][33];
    const int b  = blockIdx.z;
    const int x0 = blockIdx.x * 32;
    const int y0 = blockIdx.y * 32;
    const float* Ab = A + (size_t)b * N_ * D_;
    bf16* Hb = Thi + (size_t)b * D_ * N_;
    bf16* Lb = Tlo + (size_t)b * D_ * N_;
    const int tx = threadIdx.x & 31;
    const int ty = threadIdx.x >> 5;
    #pragma unroll
    for (int j = 0; j < 4; ++j)
        t[ty + 8 * j][tx] = Ab[(size_t)(y0 + ty + 8 * j) * D_ + x0 + tx];
    __syncthreads();
    #pragma unroll
    for (int j = 0; j < 4; ++j) {
        float val = t[tx][ty + 8 * j];
        bf16 hi = __float2bfloat16(val);
        const size_t off = (size_t)(x0 + ty + 8 * j) * N_ + y0 + tx;
        Hb[off] = hi;
        Lb[off] = __float2bfloat16(val - __bfloat162float(hi));
    }
}

// ===========================================================================
extern "C" void kernel_launch(void* const* d_in, const int* in_sizes, int n_in,
                              void* d_out, int out_size)
{
    const float* text = (const float*)d_in[0];
    const float* adj  = (const float*)d_in[1];
    const float* Wq   = (const float*)d_in[2];
    const float* bq   = (const float*)d_in[3];
    const float* Wk   = (const float*)d_in[4];
    const float* bk   = (const float*)d_in[5];
    const float* Wv   = (const float*)d_in[6];
    const float* bv   = (const float*)d_in[7];

    float* out     = (float*)d_out;
    float* new_adj = out + (long long)B_ * N_ * D_;

    bf16 *pth, *ptl, *pwth, *pwtl, *pqb, *pkb, *pvth, *pvtl, *pattn, *padjT;
    float *pv, *ps;
    cudaGetSymbolAddress((void**)&pth,  g_texth);
    cudaGetSymbolAddress((void**)&ptl,  g_textl);
    cudaGetSymbolAddress((void**)&pwth, g_wth);
    cudaGetSymbolAddress((void**)&pwtl, g_wtl);
    cudaGetSymbolAddress((void**)&pqb,  g_qb);
    cudaGetSymbolAddress((void**)&pkb,  g_kb);
    cudaGetSymbolAddress((void**)&pv,   g_v);
    cudaGetSymbolAddress((void**)&ps,   g_s);
    cudaGetSymbolAddress((void**)&pvth, g_vth);
    cudaGetSymbolAddress((void**)&pvtl, g_vtl);
    cudaGetSymbolAddress((void**)&pattn, g_attn);
    cudaGetSymbolAddress((void**)&padjT, g_adjT);

    bf16* psb = (bf16*)ps;    // bf16 scores alias

    const int SMEM_G1 = 2 * 2 * HTILE + 1024;
    const int SMEM_G2 = 2 * 3 * HTILE + 1024;
    const int SMEM_G3 = 2 * 4 * HTILE + 1024;
    cudaFuncSetAttribute((const void*)hmma_g<1, 0, bf16>,
                         cudaFuncAttributeMaxDynamicSharedMemorySize, SMEM_G1);
    cudaFuncSetAttribute((const void*)hmma_g<2, 1, bf16>,
                         cudaFuncAttributeMaxDynamicSharedMemorySize, SMEM_G2);
    cudaFuncSetAttribute((const void*)hmma_g<3, 1, float>,
                         cudaFuncAttributeMaxDynamicSharedMemorySize, SMEM_G3);
    cudaFuncSetAttribute((const void*)hmma_p4,
                         cudaFuncAttributeMaxDynamicSharedMemorySize, SMEM_P4);
    cudaFuncSetAttribute((const void*)hmma_out2,
                         cudaFuncAttributeMaxDynamicSharedMemorySize, SMEM_P5);

    const dim3 t(256);
    const long long sQ = (long long)N_ * D_;
    const long long sS = (long long)N_ * N_;

    // pre: split text; transpose+split weights
    {
        const size_t n4 = (size_t)B_ * N_ * D_ / 4;
        split_f32<<<(unsigned)((n4 + 255) / 256), t>>>(text, pth, ptl, n4);
        dim3 g(D_ / 32, D_ / 32, 1);
        wtrans_split<<<g, t>>>(Wq, pwth,               pwtl);
        wtrans_split<<<g, t>>>(Wk, pwth + D_ * D_,     pwtl + D_ * D_);
        wtrans_split<<<g, t>>>(Wv, pwth + 2 * D_ * D_, pwtl + 2 * D_ * D_);
    }

    // adjT (independent)
    {
        dim3 g(N_ / 32, N_ / 32, B_);
        transpose_bf16<<<g, t>>>(adj, padjT);
    }

    // pass 1: projections via HMMA
    {
        dim3 g(D_ / 128, (B_ * N_) / 128, 1);
        hmma_g<2, 1, bf16><<<g, t, SMEM_G2>>>(
            pth, ptl, pwth, nullptr, bq, pqb, D_ / 64, D_, D_, D_, 0, 0, 0);
        hmma_g<2, 1, bf16><<<g, t, SMEM_G2>>>(
            pth, ptl, pwth + D_ * D_, nullptr, bk, pkb, D_ / 64, D_, D_, D_, 0, 0, 0);
        hmma_g<3, 1, float><<<g, t, SMEM_G3>>>(
            pth, ptl, pwth + 2 * D_ * D_, pwtl + 2 * D_ * D_, bv, pv,
            D_ / 64, D_, D_, D_, 0, 0, 0);
    }

    // v^T split
    {
        dim3 g(D_ / 32, N_ / 32, B_);
        transpose_split<<<g, t>>>(pv, pvth, pvtl);
    }

    // pass 2: S = q @ k^T -> bf16
    {
        dim3 g(N_ / 128, N_ / 128, B_);
        hmma_g<1, 0, bf16><<<g, t, SMEM_G1>>>(
            pqb, nullptr, pkb, nullptr, nullptr, psb,
            D_ / 64, D_, D_, N_, sQ, sQ, sS);
    }

    // pass 3: softmax
    softmax_bf16<<<B_ * N_, t>>>(psb, pattn, 1.0f / 16.0f);

    // pass 4: new_adj = attn @ adjT^T  (3-stage pipeline, fp32 out only)
    {
        dim3 g(N_ / 256, N_ / 128, B_);
        hmma_p4<<<g, t, SMEM_P4>>>(pattn, padjT, new_adj);
    }

    // pass 5: out = split(new_adj) @ (vth+vtl)^T  (split done in-kernel)
    {
        dim3 g(D_ / 128, N_ / 128, B_);
        hmma_out2<<<g, t, SMEM_P5>>>(new_adj, pvth, pvtl, out);
    }
}

// round 8
// speedup vs baseline: 4.9580x; 1.0290x over previous
#include <cuda_runtime.h>
#include <cuda_bf16.h>
#include <cstdint>

// ---------------------------------------------------------------------------
// AttentionGNN Round 7 (from R6):
//   - softmax: warp-per-row (shfl reductions, no block syncs)
//   - q,k projections fused into ONE HMMA launch (N=512, interleaved qk buf)
//   - 3x wtrans_split merged into one launch (grid.z)
//   pass4 / pass5 unchanged from R6.
// ---------------------------------------------------------------------------

#define B_   8
#define N_   2048
#define D_   256

typedef __nv_bfloat16 bf16;

// Scratch (device globals)
__device__ bf16  g_texth[(size_t)B_ * N_ * D_];
__device__ bf16  g_textl[(size_t)B_ * N_ * D_];
__device__ bf16  g_wth[3 * D_ * D_];            // WqT,WkT,WvT hi (concat rows)
__device__ bf16  g_wtl[3 * D_ * D_];
__device__ bf16  g_qkb[(size_t)B_ * N_ * 512];  // interleaved q|k per row
__device__ float g_v  [(size_t)B_ * N_ * D_];
__device__ bf16  g_vth[(size_t)B_ * D_ * N_];
__device__ bf16  g_vtl[(size_t)B_ * D_ * N_];
__device__ float g_s  [(size_t)B_ * N_ * N_];   // bf16 scores alias
__device__ bf16  g_attn[(size_t)B_ * N_ * N_];
__device__ bf16  g_adjT[(size_t)B_ * N_ * N_];

// ===========================================================================
// helpers
// ===========================================================================
__device__ __forceinline__ uint32_t smem_u32(const void* p) {
    uint32_t a;
    asm("{ .reg .u64 t; cvta.to.shared.u64 t, %1; cvt.u32.u64 %0, t; }"
        : "=r"(a) : "l"(p));
    return a;
}

#define SMEM_SWIZZLE_128B(off) ((off) ^ (((off) >> 3) & 0x70))

#define CP_ASYNC_16(dst, src) \
    asm volatile("cp.async.cg.shared.global [%0], [%1], 16;" \
                 :: "r"(dst), "l"(src) : "memory")
#define CP_ASYNC_COMMIT() asm volatile("cp.async.commit_group;" ::: "memory")
#define CP_ASYNC_WAIT_ALL() asm volatile("cp.async.wait_group 0;" ::: "memory")
#define CP_ASYNC_WAIT_1()  asm volatile("cp.async.wait_group 1;" ::: "memory")

#define LDMATRIX_X4(r0, r1, r2, r3, addr) \
    asm volatile("ldmatrix.sync.aligned.m8n8.x4.shared.b16 {%0,%1,%2,%3}, [%4];" \
                 : "=r"(r0), "=r"(r1), "=r"(r2), "=r"(r3) : "r"(addr))

#define MMA_BF16(d, a, b) \
    asm volatile("mma.sync.aligned.m16n8k16.row.col.f32.bf16.bf16.f32 " \
                 "{%0,%1,%2,%3}, {%4,%5,%6,%7}, {%8,%9}, {%0,%1,%2,%3};" \
                 : "+f"((d)[0]), "+f"((d)[1]), "+f"((d)[2]), "+f"((d)[3]) \
                 : "r"((a)[0]), "r"((a)[1]), "r"((a)[2]), "r"((a)[3]), \
                   "r"((b)[0]), "r"((b)[1]))

#define HTILE 16384

template <int ROWS>
__device__ __forceinline__ void load_tileR(
    uint32_t s, const char* gbase, int ldBytes, int tid)
{
    #pragma unroll
    for (int i = 0; i < ROWS / 32; ++i) {
        int id  = tid + 256 * i;
        int row = id >> 3;
        int c   = (id & 7) * 16;
        CP_ASYNC_16(s + SMEM_SWIZZLE_128B(row * 128 + c),
                    gbase + (size_t)row * ldBytes + c);
    }
}

__device__ __forceinline__ void store2(float* p, float a, float b) {
    *(float2*)p = make_float2(a, b);
}
__device__ __forceinline__ void store2(bf16* p, float a, float b) {
    __nv_bfloat162 h;
    h.x = __float2bfloat16(a);
    h.y = __float2bfloat16(b);
    *(__nv_bfloat162*)p = h;
}

// ===========================================================================
// Generic NT HMMA GEMM, CTA 128x128, warps 2(m)x4(n), warp tile 64x32.
//   TERMS=1: Ah@Bh   TERMS=2: +Al@Bh   TERMS=3: +Ah@Bl
// Bias: per-CTA pointer select: n0<256 -> bias, else bias2 (col-256).
// ===========================================================================
template <int TERMS, int BIAS, typename OutT>
__global__ void __launch_bounds__(256, TERMS == 1 ? 2 : 1)
hmma_g(const bf16* __restrict__ Ah, const bf16* __restrict__ Al,
       const bf16* __restrict__ Bh, const bf16* __restrict__ Bl,
       const float* __restrict__ bias, const float* __restrict__ bias2,
       OutT* __restrict__ C,
       int kIters, int ldA, int ldB, int ldC,
       long long sA, long long sB, long long sC)
{
    extern __shared__ char dsm[];
    const uint32_t base = (smem_u32(dsm) + 1023) & ~1023u;
    constexpr int TPB = (TERMS == 1) ? 2 : (TERMS == 2 ? 3 : 4);
    constexpr uint32_t OAL = HTILE;
    constexpr uint32_t OBH = (TERMS == 1) ? HTILE : 2u * HTILE;
    constexpr uint32_t OBL = 3u * HTILE;

    const int tid  = threadIdx.x;
    const int lane = tid & 31;
    const int wid  = tid >> 5;
    const int wm0  = (wid & 1) * 64;
    const int wn0  = (wid >> 1) * 32;
    const int lr   = lane & 15;
    const int lc   = lane >> 4;

    const int b  = blockIdx.z;
    const int m0 = blockIdx.y * 128;
    const int n0 = blockIdx.x * 128;
    const char* Ahb = (const char*)(Ah + (size_t)b * sA + (size_t)m0 * ldA);
    const char* Alb = (TERMS >= 2)
        ? (const char*)(Al + (size_t)b * sA + (size_t)m0 * ldA) : nullptr;
    const char* Bhb = (const char*)(Bh + (size_t)b * sB + (size_t)n0 * ldB);
    const char* Blb = (TERMS == 3)
        ? (const char*)(Bl + (size_t)b * sB + (size_t)n0 * ldB) : nullptr;
    const int ldAB = ldA * 2;
    const int ldBB = ldB * 2;

    float acc[4][4][4];
    #pragma unroll
    for (int i = 0; i < 4; ++i)
        #pragma unroll
        for (int j = 0; j < 4; ++j)
            #pragma unroll
            for (int r = 0; r < 4; ++r) acc[i][j][r] = 0.0f;

    load_tileR<128>(base, Ahb, ldAB, tid);
    if (TERMS >= 2) load_tileR<128>(base + OAL, Alb, ldAB, tid);
    load_tileR<128>(base + OBH, Bhb, ldBB, tid);
    if (TERMS == 3) load_tileR<128>(base + OBL, Blb, ldBB, tid);
    CP_ASYNC_COMMIT();
    CP_ASYNC_WAIT_ALL();
    __syncthreads();

    for (int kt = 0; kt < kIters; ++kt) {
        const int buf = kt & 1;
        const uint32_t cAh = base + buf * (TPB * HTILE);
        const uint32_t cAl = cAh + OAL;
        const uint32_t cBh = cAh + OBH;
        const uint32_t cBl = cAh + OBL;

        if (kt + 1 < kIters) {
            const uint32_t nx = base + (buf ^ 1) * (TPB * HTILE);
            const size_t ko = (size_t)(kt + 1) * 128;
            load_tileR<128>(nx, Ahb + ko, ldAB, tid);
            if (TERMS >= 2) load_tileR<128>(nx + OAL, Alb + ko, ldAB, tid);
            load_tileR<128>(nx + OBH, Bhb + ko, ldBB, tid);
            if (TERMS == 3) load_tileR<128>(nx + OBL, Blb + ko, ldBB, tid);
            CP_ASYNC_COMMIT();
        }

        #pragma unroll
        for (int ks = 0; ks < 4; ++ks) {
            uint32_t afh[4][4], afl[4][4];
            uint32_t bfh[4][2], bfl[4][2];
            const int csel = ks * 2 + lc;

            #pragma unroll
            for (int mi = 0; mi < 4; ++mi) {
                const int row = wm0 + mi * 16 + lr;
                const uint32_t so = SMEM_SWIZZLE_128B(row * 128 + csel * 16);
                LDMATRIX_X4(afh[mi][0], afh[mi][1], afh[mi][2], afh[mi][3], cAh + so);
                if (TERMS >= 2)
                    LDMATRIX_X4(afl[mi][0], afl[mi][1], afl[mi][2], afl[mi][3], cAl + so);
            }
            #pragma unroll
            for (int nb = 0; nb < 2; ++nb) {
                const int row = wn0 + nb * 16 + lr;
                const uint32_t so = SMEM_SWIZZLE_128B(row * 128 + csel * 16);
                uint32_t r0, r1, r2, r3;
                LDMATRIX_X4(r0, r1, r2, r3, cBh + so);
                bfh[nb * 2][0]     = r0;  bfh[nb * 2][1]     = r2;
                bfh[nb * 2 + 1][0] = r1;  bfh[nb * 2 + 1][1] = r3;
                if (TERMS == 3) {
                    LDMATRIX_X4(r0, r1, r2, r3, cBl + so);
                    bfl[nb * 2][0]     = r0;  bfl[nb * 2][1]     = r2;
                    bfl[nb * 2 + 1][0] = r1;  bfl[nb * 2 + 1][1] = r3;
                }
            }

            #pragma unroll
            for (int mi = 0; mi < 4; ++mi)
                #pragma unroll
                for (int nj = 0; nj < 4; ++nj) {
                    MMA_BF16(acc[mi][nj], afh[mi], bfh[nj]);
                    if (TERMS >= 2) MMA_BF16(acc[mi][nj], afl[mi], bfh[nj]);
                    if (TERMS == 3) MMA_BF16(acc[mi][nj], afh[mi], bfl[nj]);
                }
        }

        CP_ASYNC_WAIT_ALL();
        __syncthreads();
    }

    const size_t crow = (size_t)b * sC + (size_t)(m0 + wm0) * ldC + n0 + wn0;
    const int r     = lane >> 2;
    const int cpair = (lane & 3) * 2;
    const float* bp = (BIAS && n0 >= 256) ? bias2 : bias;
    const int cbase = (n0 & 255) + wn0;
    #pragma unroll
    for (int mi = 0; mi < 4; ++mi) {
        #pragma unroll
        for (int nj = 0; nj < 4; ++nj) {
            float v0 = acc[mi][nj][0], v1 = acc[mi][nj][1];
            float v2 = acc[mi][nj][2], v3 = acc[mi][nj][3];
            if (BIAS) {
                const int col = cbase + nj * 8 + cpair;
                const float b0 = bp[col], b1 = bp[col + 1];
                v0 += b0; v1 += b1; v2 += b0; v3 += b1;
            }
            const size_t off0 = crow + (size_t)(mi * 16 + r) * ldC + nj * 8 + cpair;
            store2(C + off0, v0, v1);
            store2(C + off0 + (size_t)8 * ldC, v2, v3);
        }
    }
}

// ===========================================================================
// Pass 4: CTA 128(m) x 256(n), warps 2x4, warp tile 64x64, K-chunk 64.
// 3-stage cp.async pipeline, fp32-only epilogue. (unchanged from R6)
// ===========================================================================
#define P4_AT 16384
#define P4_BT 32768
#define P4_BUF (P4_AT + P4_BT)
#define SMEM_P4 (3 * P4_BUF + 1024)

__global__ void __launch_bounds__(256)
hmma_p4(const bf16* __restrict__ A, const bf16* __restrict__ Bt,
        float* __restrict__ C)
{
    extern __shared__ char dsm[];
    const uint32_t base = (smem_u32(dsm) + 1023) & ~1023u;

    const int tid  = threadIdx.x;
    const int lane = tid & 31;
    const int wid  = tid >> 5;
    const int wm0  = (wid & 1) * 64;
    const int wn0  = (wid >> 1) * 64;
    const int lr   = lane & 15;
    const int lc   = lane >> 4;

    const int b  = blockIdx.z;
    const int m0 = blockIdx.y * 128;
    const int n0 = blockIdx.x * 256;
    const char* Ab = (const char*)(A  + ((size_t)b * N_ + m0) * N_);
    const char* Bb = (const char*)(Bt + ((size_t)b * N_ + n0) * N_);
    const int ld = N_ * 2;

    float acc[4][8][4];
    #pragma unroll
    for (int i = 0; i < 4; ++i)
        #pragma unroll
        for (int j = 0; j < 8; ++j)
            #pragma unroll
            for (int r = 0; r < 4; ++r) acc[i][j][r] = 0.0f;

    const int KITER = N_ / 64;

    load_tileR<128>(base,         Ab, ld, tid);
    load_tileR<256>(base + P4_AT, Bb, ld, tid);
    CP_ASYNC_COMMIT();
    load_tileR<128>(base + P4_BUF,         Ab + 128, ld, tid);
    load_tileR<256>(base + P4_BUF + P4_AT, Bb + 128, ld, tid);
    CP_ASYNC_COMMIT();

    for (int kt = 0; kt < KITER; ++kt) {
        if (kt + 1 < KITER) { CP_ASYNC_WAIT_1(); } else { CP_ASYNC_WAIT_ALL(); }
        __syncthreads();

        if (kt + 2 < KITER) {
            const uint32_t nx = base + ((kt + 2) % 3) * P4_BUF;
            const size_t ko = (size_t)(kt + 2) * 128;
            load_tileR<128>(nx,         Ab + ko, ld, tid);
            load_tileR<256>(nx + P4_AT, Bb + ko, ld, tid);
            CP_ASYNC_COMMIT();
        }

        const uint32_t cA = base + (kt % 3) * P4_BUF;
        const uint32_t cB = cA + P4_AT;

        #pragma unroll
        for (int ks = 0; ks < 4; ++ks) {
            uint32_t af[4][4];
            uint32_t bfr[8][2];
            const int csel = ks * 2 + lc;

            #pragma unroll
            for (int mi = 0; mi < 4; ++mi) {
                const int row = wm0 + mi * 16 + lr;
                LDMATRIX_X4(af[mi][0], af[mi][1], af[mi][2], af[mi][3],
                            cA + SMEM_SWIZZLE_128B(row * 128 + csel * 16));
            }
            #pragma unroll
            for (int nb = 0; nb < 4; ++nb) {
                const int row = wn0 + nb * 16 + lr;
                uint32_t r0, r1, r2, r3;
                LDMATRIX_X4(r0, r1, r2, r3,
                            cB + SMEM_SWIZZLE_128B(row * 128 + csel * 16));
                bfr[nb * 2][0]     = r0;  bfr[nb * 2][1]     = r2;
                bfr[nb * 2 + 1][0] = r1;  bfr[nb * 2 + 1][1] = r3;
            }

            #pragma unroll
            for (int mi = 0; mi < 4; ++mi)
                #pragma unroll
                for (int nj = 0; nj < 8; ++nj)
                    MMA_BF16(acc[mi][nj], af[mi], bfr[nj]);
        }
    }

    const size_t crow = ((size_t)b * N_ + m0 + wm0) * N_ + n0 + wn0;
    const int r     = lane >> 2;
    const int cpair = (lane & 3) * 2;
    #pragma unroll
    for (int mi = 0; mi < 4; ++mi) {
        #pragma unroll
        for (int nj = 0; nj < 8; ++nj) {
            const size_t off0 = crow + (size_t)(mi * 16 + r) * N_ + nj * 8 + cpair;
            *(float2*)(C + off0) = make_float2(acc[mi][nj][0], acc[mi][nj][1]);
            *(float2*)(C + off0 + (size_t)8 * N_) =
                make_float2(acc[mi][nj][2], acc[mi][nj][3]);
        }
    }
}

// ===========================================================================
// Pass 5: out = (Ah+Al) @ (Bh+Bl)^T, A split in-kernel from fp32. (R6)
// ===========================================================================
#define SMEM_P5 (2 * 4 * HTILE + 1024)

__global__ void __launch_bounds__(256)
hmma_out2(const float* __restrict__ A,
          const bf16* __restrict__ Bh,
          const bf16* __restrict__ Bl,
          float* __restrict__ C)
{
    extern __shared__ char dsm[];
    const uint32_t base = (smem_u32(dsm) + 1023) & ~1023u;
    char* dbase = dsm + (base - smem_u32(dsm));

    const int tid  = threadIdx.x;
    const int lane = tid & 31;
    const int wid  = tid >> 5;
    const int wm0  = (wid & 1) * 64;
    const int wn0  = (wid >> 1) * 32;
    const int lr   = lane & 15;
    const int lc   = lane >> 4;

    const int b  = blockIdx.z;
    const int m0 = blockIdx.y * 128;
    const int n0 = blockIdx.x * 128;
    const char* Ab  = (const char*)(A  + ((size_t)b * N_ + m0) * N_);
    const char* Bhb = (const char*)(Bh + ((size_t)b * D_ + n0) * N_);
    const char* Blb = (const char*)(Bl + ((size_t)b * D_ + n0) * N_);
    const int ldA = N_ * 4;
    const int ldB = N_ * 2;

    float4 ar[8];

    auto ldg_A = [&](int kt) {
        #pragma unroll
        for (int i = 0; i < 8; ++i) {
            const int id  = tid + 256 * i;
            const int row = id >> 4;
            const int c16 = id & 15;
            ar[i] = *(const float4*)(Ab + (size_t)row * ldA + (size_t)kt * 256
                                        + c16 * 16);
        }
    };
    auto sts_A = [&](int buf) {
        char* sAh = dbase + buf * (4 * HTILE);
        char* sAl = sAh + HTILE;
        #pragma unroll
        for (int i = 0; i < 8; ++i) {
            const int id  = tid + 256 * i;
            const int row = id >> 4;
            const int c16 = id & 15;
            const uint32_t sw = SMEM_SWIZZLE_128B(row * 128 + c16 * 8);
            const float f[4] = {ar[i].x, ar[i].y, ar[i].z, ar[i].w};
            __nv_bfloat162 hv[2], lv[2];
            #pragma unroll
            for (int j = 0; j < 2; ++j) {
                bf16 h0 = __float2bfloat16(f[2 * j]);
                bf16 h1 = __float2bfloat16(f[2 * j + 1]);
                hv[j].x = h0; hv[j].y = h1;
                lv[j].x = __float2bfloat16(f[2 * j]     - __bfloat162float(h0));
                lv[j].y = __float2bfloat16(f[2 * j + 1] - __bfloat162float(h1));
            }
            *(uint2*)(sAh + sw) = *(uint2*)hv;
            *(uint2*)(sAl + sw) = *(uint2*)lv;
        }
    };

    float acc[4][4][4];
    #pragma unroll
    for (int i = 0; i < 4; ++i)
        #pragma unroll
        for (int j = 0; j < 4; ++j)
            #pragma unroll
            for (int r = 0; r < 4; ++r) acc[i][j][r] = 0.0f;

    load_tileR<128>(base + 2 * HTILE, Bhb, ldB, tid);
    load_tileR<128>(base + 3 * HTILE, Blb, ldB, tid);
    CP_ASYNC_COMMIT();
    ldg_A(0);
    sts_A(0);
    CP_ASYNC_WAIT_ALL();
    __syncthreads();

    const int KITER = N_ / 64;
    for (int kt = 0; kt < KITER; ++kt) {
        const int buf = kt & 1;
        const uint32_t cAh = base + buf * (4 * HTILE);
        const uint32_t cAl = cAh + HTILE;
        const uint32_t cBh = cAh + 2 * HTILE;
        const uint32_t cBl = cAh + 3 * HTILE;

        if (kt + 1 < KITER) {
            const uint32_t nx = base + (buf ^ 1) * (4 * HTILE);
            load_tileR<128>(nx + 2 * HTILE, Bhb + (size_t)(kt + 1) * 128, ldB, tid);
            load_tileR<128>(nx + 3 * HTILE, Blb + (size_t)(kt + 1) * 128, ldB, tid);
            CP_ASYNC_COMMIT();
            ldg_A(kt + 1);
        }

        #pragma unroll
        for (int ks = 0; ks < 4; ++ks) {
            uint32_t afh[4][4], afl[4][4];
            uint32_t bfh[4][2], bfl[4][2];
            const int csel = ks * 2 + lc;

            #pragma unroll
            for (int mi = 0; mi < 4; ++mi) {
                const int row = wm0 + mi * 16 + lr;
                const uint32_t so = SMEM_SWIZZLE_128B(row * 128 + csel * 16);
                LDMATRIX_X4(afh[mi][0], afh[mi][1], afh[mi][2], afh[mi][3], cAh + so);
                LDMATRIX_X4(afl[mi][0], afl[mi][1], afl[mi][2], afl[mi][3], cAl + so);
            }
            #pragma unroll
            for (int nb = 0; nb < 2; ++nb) {
                const int row = wn0 + nb * 16 + lr;
                const uint32_t so = SMEM_SWIZZLE_128B(row * 128 + csel * 16);
                uint32_t r0, r1, r2, r3;
                LDMATRIX_X4(r0, r1, r2, r3, cBh + so);
                bfh[nb * 2][0]     = r0;  bfh[nb * 2][1]     = r2;
                bfh[nb * 2 + 1][0] = r1;  bfh[nb * 2 + 1][1] = r3;
                LDMATRIX_X4(r0, r1, r2, r3, cBl + so);
                bfl[nb * 2][0]     = r0;  bfl[nb * 2][1]     = r2;
                bfl[nb * 2 + 1][0] = r1;  bfl[nb * 2 + 1][1] = r3;
            }

            #pragma unroll
            for (int mi = 0; mi < 4; ++mi)
                #pragma unroll
                for (int nj = 0; nj < 4; ++nj) {
                    MMA_BF16(acc[mi][nj], afh[mi], bfh[nj]);
                    MMA_BF16(acc[mi][nj], afl[mi], bfh[nj]);
                    MMA_BF16(acc[mi][nj], afh[mi], bfl[nj]);
                }
        }

        if (kt + 1 < KITER) {
            __syncthreads();
            sts_A(buf ^ 1);
            CP_ASYNC_WAIT_ALL();
            __syncthreads();
        }
    }

    float* Cb = C + ((size_t)b * N_ + m0 + wm0) * D_ + n0 + wn0;
    const int r     = lane >> 2;
    const int cpair = (lane & 3) * 2;
    #pragma unroll
    for (int mi = 0; mi < 4; ++mi) {
        #pragma unroll
        for (int nj = 0; nj < 4; ++nj) {
            float* p = Cb + (size_t)(mi * 16 + r) * D_ + nj * 8 + cpair;
            *(float2*)p            = make_float2(acc[mi][nj][0], acc[mi][nj][1]);
            *(float2*)(p + 8 * D_) = make_float2(acc[mi][nj][2], acc[mi][nj][3]);
        }
    }
}

// ===========================================================================
// split fp32 -> hi/lo bf16
// ===========================================================================
__global__ __launch_bounds__(256)
void split_f32(const float* __restrict__ X, bf16* __restrict__ H,
               bf16* __restrict__ L, size_t n4)
{
    size_t i = (size_t)blockIdx.x * blockDim.x + threadIdx.x;
    if (i >= n4) return;
    float4 v = ((const float4*)X)[i];
    float f[4] = {v.x, v.y, v.z, v.w};
    __nv_bfloat162 hh[2], ll[2];
    #pragma unroll
    for (int j = 0; j < 2; ++j) {
        bf16 h0 = __float2bfloat16(f[2 * j]);
        bf16 h1 = __float2bfloat16(f[2 * j + 1]);
        hh[j].x = h0; hh[j].y = h1;
        ll[j].x = __float2bfloat16(f[2 * j]     - __bfloat162float(h0));
        ll[j].y = __float2bfloat16(f[2 * j + 1] - __bfloat162float(h1));
    }
    ((uint2*)H)[i] = *(uint2*)hh;
    ((uint2*)L)[i] = *(uint2*)ll;
}

// ===========================================================================
// W [256][256] fp32 -> W^T hi/lo bf16, 3 matrices in one launch (grid.z)
// ===========================================================================
__global__ __launch_bounds__(256)
void wtrans_split3(const float* __restrict__ W0, const float* __restrict__ W1,
                   const float* __restrict__ W2,
                   bf16* __restrict__ Th, bf16* __restrict__ Tl)
{
    __shared__ float t[32][33];
    const int z = blockIdx.z;
    const float* W = (z == 0) ? W0 : (z == 1) ? W1 : W2;
    bf16* Thz = Th + z * D_ * D_;
    bf16* Tlz = Tl + z * D_ * D_;
    const int x0 = blockIdx.x * 32;
    const int y0 = blockIdx.y * 32;
    const int tx = threadIdx.x & 31;
    const int ty = threadIdx.x >> 5;
    #pragma unroll
    for (int j = 0; j < 4; ++j)
        t[ty + 8 * j][tx] = W[(y0 + ty + 8 * j) * D_ + x0 + tx];
    __syncthreads();
    #pragma unroll
    for (int j = 0; j < 4; ++j) {
        float val = t[tx][ty + 8 * j];
        bf16 hi = __float2bfloat16(val);
        const int off = (x0 + ty + 8 * j) * D_ + y0 + tx;
        Thz[off] = hi;
        Tlz[off] = __float2bfloat16(val - __bfloat162float(hi));
    }
}

// ===========================================================================
// Warp-per-row softmax: 8 warps/block, 1 row/warp, shfl reductions.
// ===========================================================================
__global__ __launch_bounds__(256)
void softmax_warp(const bf16* __restrict__ S, bf16* __restrict__ O, float scale)
{
    const int lane = threadIdx.x & 31;
    const int w    = threadIdx.x >> 5;
    const size_t row = (size_t)blockIdx.x * 8 + w;
    const uint4* p = (const uint4*)(S + row * N_);
    uint4* o       = (uint4*)(O + row * N_);

    float vals[64];
    float m = -1e30f;
    #pragma unroll
    for (int c = 0; c < 8; ++c) {
        uint4 raw = p[c * 32 + lane];
        __nv_bfloat162* pr = (__nv_bfloat162*)&raw;
        #pragma unroll
        for (int i = 0; i < 4; ++i) {
            float2 f = __bfloat1622float2(pr[i]);
            vals[c * 8 + 2 * i]     = f.x * scale;
            vals[c * 8 + 2 * i + 1] = f.y * scale;
            m = fmaxf(m, fmaxf(f.x * scale, f.y * scale));
        }
    }
    #pragma unroll
    for (int s = 16; s > 0; s >>= 1)
        m = fmaxf(m, __shfl_xor_sync(0xFFFFFFFFu, m, s));

    float sum = 0.0f;
    #pragma unroll
    for (int i = 0; i < 64; ++i) {
        vals[i] = __expf(vals[i] - m);
        sum += vals[i];
    }
    #pragma unroll
    for (int s = 16; s > 0; s >>= 1)
        sum += __shfl_xor_sync(0xFFFFFFFFu, sum, s);
    const float inv = 1.0f / sum;

    #pragma unroll
    for (int c = 0; c < 8; ++c) {
        uint4 outv;
        __nv_bfloat162* po = (__nv_bfloat162*)&outv;
        #pragma unroll
        for (int i = 0; i < 4; ++i) {
            po[i].x = __float2bfloat16(vals[c * 8 + 2 * i] * inv);
            po[i].y = __float2bfloat16(vals[c * 8 + 2 * i + 1] * inv);
        }
        o[c * 32 + lane] = outv;
    }
}

// ===========================================================================
// adj fp32 [b][k][n] -> adjT bf16 [b][n][k]
// ===========================================================================
__global__ __launch_bounds__(256)
void transpose_bf16(const float* __restrict__ A, bf16* __restrict__ T)
{
    __shared__ float t[32][33];
    const int b  = blockIdx.z;
    const int x0 = blockIdx.x * 32;
    const int y0 = blockIdx.y * 32;
    const float* Ab = A + (size_t)b * N_ * N_;
    bf16* Tb = T + (size_t)b * N_ * N_;
    const int tx = threadIdx.x & 31;
    const int ty = threadIdx.x >> 5;
    #pragma unroll
    for (int j = 0; j < 4; ++j)
        t[ty + 8 * j][tx] = Ab[(size_t)(y0 + ty + 8 * j) * N_ + x0 + tx];
    __syncthreads();
    #pragma unroll
    for (int j = 0; j < 4; ++j)
        Tb[(size_t)(x0 + ty + 8 * j) * N_ + y0 + tx] =
            __float2bfloat16(t[tx][ty + 8 * j]);
}

// ===========================================================================
// v fp32 [b][n][d] -> vT hi/lo bf16 [b][d][n]
// ===========================================================================
__global__ __launch_bounds__(256)
void transpose_split(const float* __restrict__ A, bf16* __restrict__ Thi,
                     bf16* __restrict__ Tlo)
{
    __shared__ float t[32][33];
    const int b  = blockIdx.z;
    const int x0 = blockIdx.x * 32;
    const int y0 = blockIdx.y * 32;
    const float* Ab = A + (size_t)b * N_ * D_;
    bf16* Hb = Thi + (size_t)b * D_ * N_;
    bf16* Lb = Tlo + (size_t)b * D_ * N_;
    const int tx = threadIdx.x & 31;
    const int ty = threadIdx.x >> 5;
    #pragma unroll
    for (int j = 0; j < 4; ++j)
        t[ty + 8 * j][tx] = Ab[(size_t)(y0 + ty + 8 * j) * D_ + x0 + tx];
    __syncthreads();
    #pragma unroll
    for (int j = 0; j < 4; ++j) {
        float val = t[tx][ty + 8 * j];
        bf16 hi = __float2bfloat16(val);
        const size_t off = (size_t)(x0 + ty + 8 * j) * N_ + y0 + tx;
        Hb[off] = hi;
        Lb[off] = __float2bfloat16(val - __bfloat162float(hi));
    }
}

// ===========================================================================
extern "C" void kernel_launch(void* const* d_in, const int* in_sizes, int n_in,
                              void* d_out, int out_size)
{
    const float* text = (const float*)d_in[0];
    const float* adj  = (const float*)d_in[1];
    const float* Wq   = (const float*)d_in[2];
    const float* bq   = (const float*)d_in[3];
    const float* Wk   = (const float*)d_in[4];
    const float* bk   = (const float*)d_in[5];
    const float* Wv   = (const float*)d_in[6];
    const float* bv   = (const float*)d_in[7];

    float* out     = (float*)d_out;
    float* new_adj = out + (long long)B_ * N_ * D_;

    bf16 *pth, *ptl, *pwth, *pwtl, *pqk, *pvth, *pvtl, *pattn, *padjT;
    float *pv, *ps;
    cudaGetSymbolAddress((void**)&pth,  g_texth);
    cudaGetSymbolAddress((void**)&ptl,  g_textl);
    cudaGetSymbolAddress((void**)&pwth, g_wth);
    cudaGetSymbolAddress((void**)&pwtl, g_wtl);
    cudaGetSymbolAddress((void**)&pqk,  g_qkb);
    cudaGetSymbolAddress((void**)&pv,   g_v);
    cudaGetSymbolAddress((void**)&ps,   g_s);
    cudaGetSymbolAddress((void**)&pvth, g_vth);
    cudaGetSymbolAddress((void**)&pvtl, g_vtl);
    cudaGetSymbolAddress((void**)&pattn, g_attn);
    cudaGetSymbolAddress((void**)&padjT, g_adjT);

    bf16* psb = (bf16*)ps;

    const int SMEM_G1 = 2 * 2 * HTILE + 1024;
    const int SMEM_G2 = 2 * 3 * HTILE + 1024;
    const int SMEM_G3 = 2 * 4 * HTILE + 1024;
    cudaFuncSetAttribute((const void*)hmma_g<1, 0, bf16>,
                         cudaFuncAttributeMaxDynamicSharedMemorySize, SMEM_G1);
    cudaFuncSetAttribute((const void*)hmma_g<2, 1, bf16>,
                         cudaFuncAttributeMaxDynamicSharedMemorySize, SMEM_G2);
    cudaFuncSetAttribute((const void*)hmma_g<3, 1, float>,
                         cudaFuncAttributeMaxDynamicSharedMemorySize, SMEM_G3);
    cudaFuncSetAttribute((const void*)hmma_p4,
                         cudaFuncAttributeMaxDynamicSharedMemorySize, SMEM_P4);
    cudaFuncSetAttribute((const void*)hmma_out2,
                         cudaFuncAttributeMaxDynamicSharedMemorySize, SMEM_P5);

    const dim3 t(256);
    const long long sQK = (long long)N_ * 512;
    const long long sS  = (long long)N_ * N_;

    // pre: split text; transpose+split all 3 weights in one launch
    {
        const size_t n4 = (size_t)B_ * N_ * D_ / 4;
        split_f32<<<(unsigned)((n4 + 255) / 256), t>>>(text, pth, ptl, n4);
        dim3 g(D_ / 32, D_ / 32, 3);
        wtrans_split3<<<g, t>>>(Wq, Wk, Wv, pwth, pwtl);
    }

    // adjT (independent)
    {
        dim3 g(N_ / 32, N_ / 32, B_);
        transpose_bf16<<<g, t>>>(adj, padjT);
    }

    // pass 1: fused q|k projection (N=512 over WqT||WkT), v projection
    {
        dim3 gqk(512 / 128, (B_ * N_) / 128, 1);   // (4, 128, 1)
        hmma_g<2, 1, bf16><<<gqk, t, SMEM_G2>>>(
            pth, ptl, pwth, nullptr, bq, bk, pqk,
            D_ / 64, D_, D_, 512, 0, 0, 0);
        dim3 gv(D_ / 128, (B_ * N_) / 128, 1);
        hmma_g<3, 1, float><<<gv, t, SMEM_G3>>>(
            pth, ptl, pwth + 2 * D_ * D_, pwtl + 2 * D_ * D_, bv, nullptr, pv,
            D_ / 64, D_, D_, D_, 0, 0, 0);
    }

    // v^T split
    {
        dim3 g(D_ / 32, N_ / 32, B_);
        transpose_split<<<g, t>>>(pv, pvth, pvtl);
    }

    // pass 2: S = q @ k^T -> bf16 (q at col 0, k at col 256 of qk buffer)
    {
        dim3 g(N_ / 128, N_ / 128, B_);
        hmma_g<1, 0, bf16><<<g, t, SMEM_G1>>>(
            pqk, nullptr, pqk + 256, nullptr, nullptr, nullptr, psb,
            D_ / 64, 512, 512, N_, sQK, sQK, sS);
    }

    // pass 3: softmax (warp per row)
    softmax_warp<<<B_ * N_ / 8, t>>>(psb, pattn, 1.0f / 16.0f);

    // pass 4: new_adj = attn @ adjT^T
    {
        dim3 g(N_ / 256, N_ / 128, B_);
        hmma_p4<<<g, t, SMEM_P4>>>(pattn, padjT, new_adj);
    }

    // pass 5: out = split(new_adj) @ (vth+vtl)^T
    {
        dim3 g(D_ / 128, N_ / 128, B_);
        hmma_out2<<<g, t, SMEM_P5>>>(new_adj, pvth, pvtl, out);
    }
}

// round 9
// speedup vs baseline: 5.2167x; 1.0522x over previous
#include <cuda_runtime.h>
#include <cuda_bf16.h>
#include <cstdint>

// ---------------------------------------------------------------------------
// AttentionGNN Round 8 (from R7):
//   - pass5: single-pass tf32 mma (m16n8k8) on fp32 new_adj / fp32 vT,
//     replacing 3-term double-bf16 (fewer tensor instrs, no hi/lo infra)
//   - transpose_split -> plain fp32 transpose (vT fp32)
//   everything else unchanged from R7.
// ---------------------------------------------------------------------------

#define B_   8
#define N_   2048
#define D_   256

typedef __nv_bfloat16 bf16;

// Scratch (device globals)
__device__ bf16  g_texth[(size_t)B_ * N_ * D_];
__device__ bf16  g_textl[(size_t)B_ * N_ * D_];
__device__ bf16  g_wth[3 * D_ * D_];            // WqT,WkT,WvT hi
__device__ bf16  g_wtl[3 * D_ * D_];
__device__ bf16  g_qkb[(size_t)B_ * N_ * 512];  // interleaved q|k per row
__device__ float g_v  [(size_t)B_ * N_ * D_];
__device__ float g_vt [(size_t)B_ * D_ * N_];   // v^T fp32
__device__ float g_s  [(size_t)B_ * N_ * N_];   // bf16 scores alias
__device__ bf16  g_attn[(size_t)B_ * N_ * N_];
__device__ bf16  g_adjT[(size_t)B_ * N_ * N_];

// ===========================================================================
// helpers
// ===========================================================================
__device__ __forceinline__ uint32_t smem_u32(const void* p) {
    uint32_t a;
    asm("{ .reg .u64 t; cvta.to.shared.u64 t, %1; cvt.u32.u64 %0, t; }"
        : "=r"(a) : "l"(p));
    return a;
}

#define SMEM_SWIZZLE_128B(off) ((off) ^ (((off) >> 3) & 0x70))

#define CP_ASYNC_16(dst, src) \
    asm volatile("cp.async.cg.shared.global [%0], [%1], 16;" \
                 :: "r"(dst), "l"(src) : "memory")
#define CP_ASYNC_COMMIT() asm volatile("cp.async.commit_group;" ::: "memory")
#define CP_ASYNC_WAIT_ALL() asm volatile("cp.async.wait_group 0;" ::: "memory")
#define CP_ASYNC_WAIT_1()  asm volatile("cp.async.wait_group 1;" ::: "memory")

#define LDMATRIX_X4(r0, r1, r2, r3, addr) \
    asm volatile("ldmatrix.sync.aligned.m8n8.x4.shared.b16 {%0,%1,%2,%3}, [%4];" \
                 : "=r"(r0), "=r"(r1), "=r"(r2), "=r"(r3) : "r"(addr))

#define MMA_BF16(d, a, b) \
    asm volatile("mma.sync.aligned.m16n8k16.row.col.f32.bf16.bf16.f32 " \
                 "{%0,%1,%2,%3}, {%4,%5,%6,%7}, {%8,%9}, {%0,%1,%2,%3};" \
                 : "+f"((d)[0]), "+f"((d)[1]), "+f"((d)[2]), "+f"((d)[3]) \
                 : "r"((a)[0]), "r"((a)[1]), "r"((a)[2]), "r"((a)[3]), \
                   "r"((b)[0]), "r"((b)[1]))

#define MMA_TF32(d, a, b) \
    asm volatile("mma.sync.aligned.m16n8k8.row.col.f32.tf32.tf32.f32 " \
                 "{%0,%1,%2,%3}, {%4,%5,%6,%7}, {%8,%9}, {%0,%1,%2,%3};" \
                 : "+f"((d)[0]), "+f"((d)[1]), "+f"((d)[2]), "+f"((d)[3]) \
                 : "r"((a)[0]), "r"((a)[1]), "r"((a)[2]), "r"((a)[3]), \
                   "r"((b)[0]), "r"((b)[1]))

__device__ __forceinline__ uint32_t f2tf32(float f) {
    uint32_t r;
    asm("cvt.rna.tf32.f32 %0, %1;" : "=r"(r) : "f"(f));
    return r;
}

#define HTILE 16384

template <int ROWS>
__device__ __forceinline__ void load_tileR(
    uint32_t s, const char* gbase, int ldBytes, int tid)
{
    #pragma unroll
    for (int i = 0; i < ROWS / 32; ++i) {
        int id  = tid + 256 * i;
        int row = id >> 3;
        int c   = (id & 7) * 16;
        CP_ASYNC_16(s + SMEM_SWIZZLE_128B(row * 128 + c),
                    gbase + (size_t)row * ldBytes + c);
    }
}

__device__ __forceinline__ void store2(float* p, float a, float b) {
    *(float2*)p = make_float2(a, b);
}
__device__ __forceinline__ void store2(bf16* p, float a, float b) {
    __nv_bfloat162 h;
    h.x = __float2bfloat16(a);
    h.y = __float2bfloat16(b);
    *(__nv_bfloat162*)p = h;
}

// ===========================================================================
// Generic NT bf16 HMMA GEMM, CTA 128x128 (unchanged from R7)
// ===========================================================================
template <int TERMS, int BIAS, typename OutT>
__global__ void __launch_bounds__(256, TERMS == 1 ? 2 : 1)
hmma_g(const bf16* __restrict__ Ah, const bf16* __restrict__ Al,
       const bf16* __restrict__ Bh, const bf16* __restrict__ Bl,
       const float* __restrict__ bias, const float* __restrict__ bias2,
       OutT* __restrict__ C,
       int kIters, int ldA, int ldB, int ldC,
       long long sA, long long sB, long long sC)
{
    extern __shared__ char dsm[];
    const uint32_t base = (smem_u32(dsm) + 1023) & ~1023u;
    constexpr int TPB = (TERMS == 1) ? 2 : (TERMS == 2 ? 3 : 4);
    constexpr uint32_t OAL = HTILE;
    constexpr uint32_t OBH = (TERMS == 1) ? HTILE : 2u * HTILE;
    constexpr uint32_t OBL = 3u * HTILE;

    const int tid  = threadIdx.x;
    const int lane = tid & 31;
    const int wid  = tid >> 5;
    const int wm0  = (wid & 1) * 64;
    const int wn0  = (wid >> 1) * 32;
    const int lr   = lane & 15;
    const int lc   = lane >> 4;

    const int b  = blockIdx.z;
    const int m0 = blockIdx.y * 128;
    const int n0 = blockIdx.x * 128;
    const char* Ahb = (const char*)(Ah + (size_t)b * sA + (size_t)m0 * ldA);
    const char* Alb = (TERMS >= 2)
        ? (const char*)(Al + (size_t)b * sA + (size_t)m0 * ldA) : nullptr;
    const char* Bhb = (const char*)(Bh + (size_t)b * sB + (size_t)n0 * ldB);
    const char* Blb = (TERMS == 3)
        ? (const char*)(Bl + (size_t)b * sB + (size_t)n0 * ldB) : nullptr;
    const int ldAB = ldA * 2;
    const int ldBB = ldB * 2;

    float acc[4][4][4];
    #pragma unroll
    for (int i = 0; i < 4; ++i)
        #pragma unroll
        for (int j = 0; j < 4; ++j)
            #pragma unroll
            for (int r = 0; r < 4; ++r) acc[i][j][r] = 0.0f;

    load_tileR<128>(base, Ahb, ldAB, tid);
    if (TERMS >= 2) load_tileR<128>(base + OAL, Alb, ldAB, tid);
    load_tileR<128>(base + OBH, Bhb, ldBB, tid);
    if (TERMS == 3) load_tileR<128>(base + OBL, Blb, ldBB, tid);
    CP_ASYNC_COMMIT();
    CP_ASYNC_WAIT_ALL();
    __syncthreads();

    for (int kt = 0; kt < kIters; ++kt) {
        const int buf = kt & 1;
        const uint32_t cAh = base + buf * (TPB * HTILE);
        const uint32_t cAl = cAh + OAL;
        const uint32_t cBh = cAh + OBH;
        const uint32_t cBl = cAh + OBL;

        if (kt + 1 < kIters) {
            const uint32_t nx = base + (buf ^ 1) * (TPB * HTILE);
            const size_t ko = (size_t)(kt + 1) * 128;
            load_tileR<128>(nx, Ahb + ko, ldAB, tid);
            if (TERMS >= 2) load_tileR<128>(nx + OAL, Alb + ko, ldAB, tid);
            load_tileR<128>(nx + OBH, Bhb + ko, ldBB, tid);
            if (TERMS == 3) load_tileR<128>(nx + OBL, Blb + ko, ldBB, tid);
            CP_ASYNC_COMMIT();
        }

        #pragma unroll
        for (int ks = 0; ks < 4; ++ks) {
            uint32_t afh[4][4], afl[4][4];
            uint32_t bfh[4][2], bfl[4][2];
            const int csel = ks * 2 + lc;

            #pragma unroll
            for (int mi = 0; mi < 4; ++mi) {
                const int row = wm0 + mi * 16 + lr;
                const uint32_t so = SMEM_SWIZZLE_128B(row * 128 + csel * 16);
                LDMATRIX_X4(afh[mi][0], afh[mi][1], afh[mi][2], afh[mi][3], cAh + so);
                if (TERMS >= 2)
                    LDMATRIX_X4(afl[mi][0], afl[mi][1], afl[mi][2], afl[mi][3], cAl + so);
            }
            #pragma unroll
            for (int nb = 0; nb < 2; ++nb) {
                const int row = wn0 + nb * 16 + lr;
                const uint32_t so = SMEM_SWIZZLE_128B(row * 128 + csel * 16);
                uint32_t r0, r1, r2, r3;
                LDMATRIX_X4(r0, r1, r2, r3, cBh + so);
                bfh[nb * 2][0]     = r0;  bfh[nb * 2][1]     = r2;
                bfh[nb * 2 + 1][0] = r1;  bfh[nb * 2 + 1][1] = r3;
                if (TERMS == 3) {
                    LDMATRIX_X4(r0, r1, r2, r3, cBl + so);
                    bfl[nb * 2][0]     = r0;  bfl[nb * 2][1]     = r2;
                    bfl[nb * 2 + 1][0] = r1;  bfl[nb * 2 + 1][1] = r3;
                }
            }

            #pragma unroll
            for (int mi = 0; mi < 4; ++mi)
                #pragma unroll
                for (int nj = 0; nj < 4; ++nj) {
                    MMA_BF16(acc[mi][nj], afh[mi], bfh[nj]);
                    if (TERMS >= 2) MMA_BF16(acc[mi][nj], afl[mi], bfh[nj]);
                    if (TERMS == 3) MMA_BF16(acc[mi][nj], afh[mi], bfl[nj]);
                }
        }

        CP_ASYNC_WAIT_ALL();
        __syncthreads();
    }

    const size_t crow = (size_t)b * sC + (size_t)(m0 + wm0) * ldC + n0 + wn0;
    const int r     = lane >> 2;
    const int cpair = (lane & 3) * 2;
    const float* bp = (BIAS && n0 >= 256) ? bias2 : bias;
    const int cbase = (n0 & 255) + wn0;
    #pragma unroll
    for (int mi = 0; mi < 4; ++mi) {
        #pragma unroll
        for (int nj = 0; nj < 4; ++nj) {
            float v0 = acc[mi][nj][0], v1 = acc[mi][nj][1];
            float v2 = acc[mi][nj][2], v3 = acc[mi][nj][3];
            if (BIAS) {
                const int col = cbase + nj * 8 + cpair;
                const float b0 = bp[col], b1 = bp[col + 1];
                v0 += b0; v1 += b1; v2 += b0; v3 += b1;
            }
            const size_t off0 = crow + (size_t)(mi * 16 + r) * ldC + nj * 8 + cpair;
            store2(C + off0, v0, v1);
            store2(C + off0 + (size_t)8 * ldC, v2, v3);
        }
    }
}

// ===========================================================================
// Pass 4: bf16 HMMA, CTA 128x256, 3-stage pipeline (unchanged from R7)
// ===========================================================================
#define P4_AT 16384
#define P4_BT 32768
#define P4_BUF (P4_AT + P4_BT)
#define SMEM_P4 (3 * P4_BUF + 1024)

__global__ void __launch_bounds__(256)
hmma_p4(const bf16* __restrict__ A, const bf16* __restrict__ Bt,
        float* __restrict__ C)
{
    extern __shared__ char dsm[];
    const uint32_t base = (smem_u32(dsm) + 1023) & ~1023u;

    const int tid  = threadIdx.x;
    const int lane = tid & 31;
    const int wid  = tid >> 5;
    const int wm0  = (wid & 1) * 64;
    const int wn0  = (wid >> 1) * 64;
    const int lr   = lane & 15;
    const int lc   = lane >> 4;

    const int b  = blockIdx.z;
    const int m0 = blockIdx.y * 128;
    const int n0 = blockIdx.x * 256;
    const char* Ab = (const char*)(A  + ((size_t)b * N_ + m0) * N_);
    const char* Bb = (const char*)(Bt + ((size_t)b * N_ + n0) * N_);
    const int ld = N_ * 2;

    float acc[4][8][4];
    #pragma unroll
    for (int i = 0; i < 4; ++i)
        #pragma unroll
        for (int j = 0; j < 8; ++j)
            #pragma unroll
            for (int r = 0; r < 4; ++r) acc[i][j][r] = 0.0f;

    const int KITER = N_ / 64;

    load_tileR<128>(base,         Ab, ld, tid);
    load_tileR<256>(base + P4_AT, Bb, ld, tid);
    CP_ASYNC_COMMIT();
    load_tileR<128>(base + P4_BUF,         Ab + 128, ld, tid);
    load_tileR<256>(base + P4_BUF + P4_AT, Bb + 128, ld, tid);
    CP_ASYNC_COMMIT();

    for (int kt = 0; kt < KITER; ++kt) {
        if (kt + 1 < KITER) { CP_ASYNC_WAIT_1(); } else { CP_ASYNC_WAIT_ALL(); }
        __syncthreads();

        if (kt + 2 < KITER) {
            const uint32_t nx = base + ((kt + 2) % 3) * P4_BUF;
            const size_t ko = (size_t)(kt + 2) * 128;
            load_tileR<128>(nx,         Ab + ko, ld, tid);
            load_tileR<256>(nx + P4_AT, Bb + ko, ld, tid);
            CP_ASYNC_COMMIT();
        }

        const uint32_t cA = base + (kt % 3) * P4_BUF;
        const uint32_t cB = cA + P4_AT;

        #pragma unroll
        for (int ks = 0; ks < 4; ++ks) {
            uint32_t af[4][4];
            uint32_t bfr[8][2];
            const int csel = ks * 2 + lc;

            #pragma unroll
            for (int mi = 0; mi < 4; ++mi) {
                const int row = wm0 + mi * 16 + lr;
                LDMATRIX_X4(af[mi][0], af[mi][1], af[mi][2], af[mi][3],
                            cA + SMEM_SWIZZLE_128B(row * 128 + csel * 16));
            }
            #pragma unroll
            for (int nb = 0; nb < 4; ++nb) {
                const int row = wn0 + nb * 16 + lr;
                uint32_t r0, r1, r2, r3;
                LDMATRIX_X4(r0, r1, r2, r3,
                            cB + SMEM_SWIZZLE_128B(row * 128 + csel * 16));
                bfr[nb * 2][0]     = r0;  bfr[nb * 2][1]     = r2;
                bfr[nb * 2 + 1][0] = r1;  bfr[nb * 2 + 1][1] = r3;
            }

            #pragma unroll
            for (int mi = 0; mi < 4; ++mi)
                #pragma unroll
                for (int nj = 0; nj < 8; ++nj)
                    MMA_BF16(acc[mi][nj], af[mi], bfr[nj]);
        }
    }

    const size_t crow = ((size_t)b * N_ + m0 + wm0) * N_ + n0 + wn0;
    const int r     = lane >> 2;
    const int cpair = (lane & 3) * 2;
    #pragma unroll
    for (int mi = 0; mi < 4; ++mi) {
        #pragma unroll
        for (int nj = 0; nj < 8; ++nj) {
            const size_t off0 = crow + (size_t)(mi * 16 + r) * N_ + nj * 8 + cpair;
            *(float2*)(C + off0) = make_float2(acc[mi][nj][0], acc[mi][nj][1]);
            *(float2*)(C + off0 + (size_t)8 * N_) =
                make_float2(acc[mi][nj][2], acc[mi][nj][3]);
        }
    }
}

// ===========================================================================
// Pass 5 (NEW): out = new_adj @ vT^T in tf32 (m16n8k8), fp32 acc.
// CTA 128(m) x 128(n=d), K-chunk 64, warps 2x4, warp tile 64x32.
// A: LDG float4 -> cvt.rna.tf32 -> STS (padded stride 68 floats).
// B: cp.async raw fp32 -> cvt after LDS.
// Padded stride 68: bank = (4*row + col) % 32 -> fragment loads conflict-free.
// ===========================================================================
#define P5T_STRIDE 68
#define P5T_TILE  (128 * P5T_STRIDE * 4)   // 34816 B
#define P5T_BUF   (2 * P5T_TILE)           // A + B per stage
#define SMEM_P5T  (2 * P5T_BUF + 1024)

__global__ void __launch_bounds__(256)
tmma_out(const float* __restrict__ A,      // new_adj fp32 [B,N,N]
         const float* __restrict__ Bt,     // vT fp32 [B,D,N]
         float* __restrict__ C)            // out [B,N,D]
{
    extern __shared__ char dsm[];
    const uint32_t base = (smem_u32(dsm) + 1023) & ~1023u;
    char* dbase = dsm + (base - smem_u32(dsm));

    const int tid  = threadIdx.x;
    const int lane = tid & 31;
    const int wid  = tid >> 5;
    const int wm0  = (wid & 1) * 64;
    const int wn0  = (wid >> 1) * 32;
    const int lg   = lane >> 2;        // group id 0..7
    const int lt   = lane & 3;         // thread-in-group

    const int b  = blockIdx.z;
    const int m0 = blockIdx.y * 128;
    const int n0 = blockIdx.x * 128;   // d offset
    const char* Ab  = (const char*)(A  + ((size_t)b * N_ + m0) * N_);
    const char* Bb  = (const char*)(Bt + ((size_t)b * D_ + n0) * N_);
    const int ldAB = N_ * 4;

    float4 ar[8];

    auto ldg_A = [&](int kt) {
        #pragma unroll
        for (int i = 0; i < 8; ++i) {
            const int id  = tid + 256 * i;
            const int row = id >> 4;
            const int c16 = id & 15;
            ar[i] = *(const float4*)(Ab + (size_t)row * ldAB
                                        + (size_t)kt * 256 + c16 * 16);
        }
    };
    auto sts_A = [&](int buf) {
        uint32_t* sA = (uint32_t*)(dbase + buf * P5T_BUF);
        #pragma unroll
        for (int i = 0; i < 8; ++i) {
            const int id  = tid + 256 * i;
            const int row = id >> 4;
            const int c16 = id & 15;
            uint4 t;
            t.x = f2tf32(ar[i].x);
            t.y = f2tf32(ar[i].y);
            t.z = f2tf32(ar[i].z);
            t.w = f2tf32(ar[i].w);
            *(uint4*)(sA + row * P5T_STRIDE + c16 * 4) = t;
        }
    };
    auto ldB = [&](int buf, int kt) {
        // cp.async vT tile 128 rows(d) x 64 k floats into padded layout
        const uint32_t sB = base + buf * P5T_BUF + P5T_TILE;
        const char* g = Bb + (size_t)kt * 256;
        #pragma unroll
        for (int i = 0; i < 8; ++i) {
            const int id  = tid + 256 * i;
            const int row = id >> 4;
            const int c16 = id & 15;
            CP_ASYNC_16(sB + row * (P5T_STRIDE * 4) + c16 * 16,
                        g + (size_t)row * ldAB + c16 * 16);
        }
    };

    float acc[4][4][4];
    #pragma unroll
    for (int i = 0; i < 4; ++i)
        #pragma unroll
        for (int j = 0; j < 4; ++j)
            #pragma unroll
            for (int r = 0; r < 4; ++r) acc[i][j][r] = 0.0f;

    // prologue: stage 0
    ldB(0, 0);
    CP_ASYNC_COMMIT();
    ldg_A(0);
    sts_A(0);
    CP_ASYNC_WAIT_ALL();
    __syncthreads();

    const int KITER = N_ / 64;   // 32
    for (int kt = 0; kt < KITER; ++kt) {
        const int buf = kt & 1;
        const uint32_t* sA = (const uint32_t*)(dbase + buf * P5T_BUF);
        const float*    sB = (const float*)(dbase + buf * P5T_BUF + P5T_TILE);

        if (kt + 1 < KITER) {
            ldB(buf ^ 1, kt + 1);
            CP_ASYNC_COMMIT();
            ldg_A(kt + 1);    // LDG overlaps compute
        }

        #pragma unroll
        for (int s = 0; s < 8; ++s) {
            const int k0 = s * 8;
            uint32_t af[4][4];
            uint32_t bf[4][2];

            #pragma unroll
            for (int mi = 0; mi < 4; ++mi) {
                const int rb = (wm0 + mi * 16 + lg) * P5T_STRIDE + k0 + lt;
                af[mi][0] = sA[rb];
                af[mi][1] = sA[rb + 8 * P5T_STRIDE];
                af[mi][2] = sA[rb + 4];
                af[mi][3] = sA[rb + 8 * P5T_STRIDE + 4];
            }
            #pragma unroll
            for (int nj = 0; nj < 4; ++nj) {
                const int rb = (wn0 + nj * 8 + lg) * P5T_STRIDE + k0 + lt;
                bf[nj][0] = f2tf32(sB[rb]);
                bf[nj][1] = f2tf32(sB[rb + 4]);
            }

            #pragma unroll
            for (int mi = 0; mi < 4; ++mi)
                #pragma unroll
                for (int nj = 0; nj < 4; ++nj)
                    MMA_TF32(acc[mi][nj], af[mi], bf[nj]);
        }

        if (kt + 1 < KITER) {
            __syncthreads();          // all warps done with buf^1 reads
            sts_A(buf ^ 1);           // A tf32 tile for kt+1
            CP_ASYNC_WAIT_ALL();      // B tile for kt+1 landed
            __syncthreads();
        }
    }

    float* Cb = C + ((size_t)b * N_ + m0 + wm0) * D_ + n0 + wn0;
    const int cpair = lt * 2;
    #pragma unroll
    for (int mi = 0; mi < 4; ++mi) {
        #pragma unroll
        for (int nj = 0; nj < 4; ++nj) {
            float* p = Cb + (size_t)(mi * 16 + lg) * D_ + nj * 8 + cpair;
            *(float2*)p            = make_float2(acc[mi][nj][0], acc[mi][nj][1]);
            *(float2*)(p + 8 * D_) = make_float2(acc[mi][nj][2], acc[mi][nj][3]);
        }
    }
}

// ===========================================================================
// split fp32 -> hi/lo bf16
// ===========================================================================
__global__ __launch_bounds__(256)
void split_f32(const float* __restrict__ X, bf16* __restrict__ H,
               bf16* __restrict__ L, size_t n4)
{
    size_t i = (size_t)blockIdx.x * blockDim.x + threadIdx.x;
    if (i >= n4) return;
    float4 v = ((const float4*)X)[i];
    float f[4] = {v.x, v.y, v.z, v.w};
    __nv_bfloat162 hh[2], ll[2];
    #pragma unroll
    for (int j = 0; j < 2; ++j) {
        bf16 h0 = __float2bfloat16(f[2 * j]);
        bf16 h1 = __float2bfloat16(f[2 * j + 1]);
        hh[j].x = h0; hh[j].y = h1;
        ll[j].x = __float2bfloat16(f[2 * j]     - __bfloat162float(h0));
        ll[j].y = __float2bfloat16(f[2 * j + 1] - __bfloat162float(h1));
    }
    ((uint2*)H)[i] = *(uint2*)hh;
    ((uint2*)L)[i] = *(uint2*)ll;
}

// ===========================================================================
// W [256][256] fp32 -> W^T hi/lo bf16, 3 matrices in one launch (grid.z)
// ===========================================================================
__global__ __launch_bounds__(256)
void wtrans_split3(const float* __restrict__ W0, const float* __restrict__ W1,
                   const float* __restrict__ W2,
                   bf16* __restrict__ Th, bf16* __restrict__ Tl)
{
    __shared__ float t[32][33];
    const int z = blockIdx.z;
    const float* W = (z == 0) ? W0 : (z == 1) ? W1 : W2;
    bf16* Thz = Th + z * D_ * D_;
    bf16* Tlz = Tl + z * D_ * D_;
    const int x0 = blockIdx.x * 32;
    const int y0 = blockIdx.y * 32;
    const int tx = threadIdx.x & 31;
    const int ty = threadIdx.x >> 5;
    #pragma unroll
    for (int j = 0; j < 4; ++j)
        t[ty + 8 * j][tx] = W[(y0 + ty + 8 * j) * D_ + x0 + tx];
    __syncthreads();
    #pragma unroll
    for (int j = 0; j < 4; ++j) {
        float val = t[tx][ty + 8 * j];
        bf16 hi = __float2bfloat16(val);
        const int off = (x0 + ty + 8 * j) * D_ + y0 + tx;
        Thz[off] = hi;
        Tlz[off] = __float2bfloat16(val - __bfloat162float(hi));
    }
}

// ===========================================================================
// Warp-per-row softmax
// ===========================================================================
__global__ __launch_bounds__(256)
void softmax_warp(const bf16* __restrict__ S, bf16* __restrict__ O, float scale)
{
    const int lane = threadIdx.x & 31;
    const int w    = threadIdx.x >> 5;
    const size_t row = (size_t)blockIdx.x * 8 + w;
    const uint4* p = (const uint4*)(S + row * N_);
    uint4* o       = (uint4*)(O + row * N_);

    float vals[64];
    float m = -1e30f;
    #pragma unroll
    for (int c = 0; c < 8; ++c) {
        uint4 raw = p[c * 32 + lane];
        __nv_bfloat162* pr = (__nv_bfloat162*)&raw;
        #pragma unroll
        for (int i = 0; i < 4; ++i) {
            float2 f = __bfloat1622float2(pr[i]);
            vals[c * 8 + 2 * i]     = f.x * scale;
            vals[c * 8 + 2 * i + 1] = f.y * scale;
            m = fmaxf(m, fmaxf(f.x * scale, f.y * scale));
        }
    }
    #pragma unroll
    for (int s = 16; s > 0; s >>= 1)
        m = fmaxf(m, __shfl_xor_sync(0xFFFFFFFFu, m, s));

    float sum = 0.0f;
    #pragma unroll
    for (int i = 0; i < 64; ++i) {
        vals[i] = __expf(vals[i] - m);
        sum += vals[i];
    }
    #pragma unroll
    for (int s = 16; s > 0; s >>= 1)
        sum += __shfl_xor_sync(0xFFFFFFFFu, sum, s);
    const float inv = 1.0f / sum;

    #pragma unroll
    for (int c = 0; c < 8; ++c) {
        uint4 outv;
        __nv_bfloat162* po = (__nv_bfloat162*)&outv;
        #pragma unroll
        for (int i = 0; i < 4; ++i) {
            po[i].x = __float2bfloat16(vals[c * 8 + 2 * i] * inv);
            po[i].y = __float2bfloat16(vals[c * 8 + 2 * i + 1] * inv);
        }
        o[c * 32 + lane] = outv;
    }
}

// ===========================================================================
// adj fp32 [b][k][n] -> adjT bf16 [b][n][k]
// ===========================================================================
__global__ __launch_bounds__(256)
void transpose_bf16(const float* __restrict__ A, bf16* __restrict__ T)
{
    __shared__ float t[32][33];
    const int b  = blockIdx.z;
    const int x0 = blockIdx.x * 32;
    const int y0 = blockIdx.y * 32;
    const float* Ab = A + (size_t)b * N_ * N_;
    bf16* Tb = T + (size_t)b * N_ * N_;
    const int tx = threadIdx.x & 31;
    const int ty = threadIdx.x >> 5;
    #pragma unroll
    for (int j = 0; j < 4; ++j)
        t[ty + 8 * j][tx] = Ab[(size_t)(y0 + ty + 8 * j) * N_ + x0 + tx];
    __syncthreads();
    #pragma unroll
    for (int j = 0; j < 4; ++j)
        Tb[(size_t)(x0 + ty + 8 * j) * N_ + y0 + tx] =
            __float2bfloat16(t[tx][ty + 8 * j]);
}

// ===========================================================================
// v fp32 [b][n][d] -> vT fp32 [b][d][n]
// ===========================================================================
__global__ __launch_bounds__(256)
void transpose_f32(const float* __restrict__ A, float* __restrict__ T)
{
    __shared__ float t[32][33];
    const int b  = blockIdx.z;
    const int x0 = blockIdx.x * 32;    // d
    const int y0 = blockIdx.y * 32;    // n
    const float* Ab = A + (size_t)b * N_ * D_;
    float* Tb = T + (size_t)b * D_ * N_;
    const int tx = threadIdx.x & 31;
    const int ty = threadIdx.x >> 5;
    #pragma unroll
    for (int j = 0; j < 4; ++j)
        t[ty + 8 * j][tx] = Ab[(size_t)(y0 + ty + 8 * j) * D_ + x0 + tx];
    __syncthreads();
    #pragma unroll
    for (int j = 0; j < 4; ++j)
        Tb[(size_t)(x0 + ty + 8 * j) * N_ + y0 + tx] = t[tx][ty + 8 * j];
}

// ===========================================================================
extern "C" void kernel_launch(void* const* d_in, const int* in_sizes, int n_in,
                              void* d_out, int out_size)
{
    const float* text = (const float*)d_in[0];
    const float* adj  = (const float*)d_in[1];
    const float* Wq   = (const float*)d_in[2];
    const float* bq   = (const float*)d_in[3];
    const float* Wk   = (const float*)d_in[4];
    const float* bk   = (const float*)d_in[5];
    const float* Wv   = (const float*)d_in[6];
    const float* bv   = (const float*)d_in[7];

    float* out     = (float*)d_out;
    float* new_adj = out + (long long)B_ * N_ * D_;

    bf16 *pth, *ptl, *pwth, *pwtl, *pqk, *pattn, *padjT;
    float *pv, *pvt, *ps;
    cudaGetSymbolAddress((void**)&pth,  g_texth);
    cudaGetSymbolAddress((void**)&ptl,  g_textl);
    cudaGetSymbolAddress((void**)&pwth, g_wth);
    cudaGetSymbolAddress((void**)&pwtl, g_wtl);
    cudaGetSymbolAddress((void**)&pqk,  g_qkb);
    cudaGetSymbolAddress((void**)&pv,   g_v);
    cudaGetSymbolAddress((void**)&pvt,  g_vt);
    cudaGetSymbolAddress((void**)&ps,   g_s);
    cudaGetSymbolAddress((void**)&pattn, g_attn);
    cudaGetSymbolAddress((void**)&padjT, g_adjT);

    bf16* psb = (bf16*)ps;

    const int SMEM_G1 = 2 * 2 * HTILE + 1024;
    const int SMEM_G2 = 2 * 3 * HTILE + 1024;
    const int SMEM_G3 = 2 * 4 * HTILE + 1024;
    cudaFuncSetAttribute((const void*)hmma_g<1, 0, bf16>,
                         cudaFuncAttributeMaxDynamicSharedMemorySize, SMEM_G1);
    cudaFuncSetAttribute((const void*)hmma_g<2, 1, bf16>,
                         cudaFuncAttributeMaxDynamicSharedMemorySize, SMEM_G2);
    cudaFuncSetAttribute((const void*)hmma_g<3, 1, float>,
                         cudaFuncAttributeMaxDynamicSharedMemorySize, SMEM_G3);
    cudaFuncSetAttribute((const void*)hmma_p4,
                         cudaFuncAttributeMaxDynamicSharedMemorySize, SMEM_P4);
    cudaFuncSetAttribute((const void*)tmma_out,
                         cudaFuncAttributeMaxDynamicSharedMemorySize, SMEM_P5T);

    const dim3 t(256);
    const long long sQK = (long long)N_ * 512;
    const long long sS  = (long long)N_ * N_;

    // pre: split text; transpose+split all 3 weights
    {
        const size_t n4 = (size_t)B_ * N_ * D_ / 4;
        split_f32<<<(unsigned)((n4 + 255) / 256), t>>>(text, pth, ptl, n4);
        dim3 g(D_ / 32, D_ / 32, 3);
        wtrans_split3<<<g, t>>>(Wq, Wk, Wv, pwth, pwtl);
    }

    // adjT (independent)
    {
        dim3 g(N_ / 32, N_ / 32, B_);
        transpose_bf16<<<g, t>>>(adj, padjT);
    }

    // pass 1: fused q|k projection; v projection (3-term, fp32 out)
    {
        dim3 gqk(512 / 128, (B_ * N_) / 128, 1);
        hmma_g<2, 1, bf16><<<gqk, t, SMEM_G2>>>(
            pth, ptl, pwth, nullptr, bq, bk, pqk,
            D_ / 64, D_, D_, 512, 0, 0, 0);
        dim3 gv(D_ / 128, (B_ * N_) / 128, 1);
        hmma_g<3, 1, float><<<gv, t, SMEM_G3>>>(
            pth, ptl, pwth + 2 * D_ * D_, pwtl + 2 * D_ * D_, bv, nullptr, pv,
            D_ / 64, D_, D_, D_, 0, 0, 0);
    }

    // v^T fp32
    {
        dim3 g(D_ / 32, N_ / 32, B_);
        transpose_f32<<<g, t>>>(pv, pvt);
    }

    // pass 2: S = q @ k^T -> bf16
    {
        dim3 g(N_ / 128, N_ / 128, B_);
        hmma_g<1, 0, bf16><<<g, t, SMEM_G1>>>(
            pqk, nullptr, pqk + 256, nullptr, nullptr, nullptr, psb,
            D_ / 64, 512, 512, N_, sQK, sQK, sS);
    }

    // pass 3: softmax (warp per row)
    softmax_warp<<<B_ * N_ / 8, t>>>(psb, pattn, 1.0f / 16.0f);

    // pass 4: new_adj = attn @ adjT^T
    {
        dim3 g(N_ / 256, N_ / 128, B_);
        hmma_p4<<<g, t, SMEM_P4>>>(pattn, padjT, new_adj);
    }

    // pass 5: out = new_adj @ vT^T  (tf32)
    {
        dim3 g(D_ / 128, N_ / 128, B_);
        tmma_out<<<g, t, SMEM_P5T>>>(new_adj, pvt, out);
    }
}